// round 1
// baseline (speedup 1.0000x reference)
#include <cuda_runtime.h>
#include <cstddef>

#define BB 4
#define CC 256
#define CKD 32
#define NN 4096
#define HH 64
#define WW 64

// ---------------- scratch (device globals; no allocation allowed) ----------------
__device__ float g_q1[BB*CKD*NN];
__device__ float g_k1[BB*CKD*NN];
__device__ float g_q2[BB*CKD*NN];
__device__ float g_k2[BB*CKD*NN];
__device__ float g_v1[BB*CC*NN];
__device__ float g_v2[BB*CC*NN];
__device__ float g_d1a[BB*CC*NN];
__device__ float g_d1b[BB*CC*NN];
__device__ float g_d3a[BB*CC*NN];
__device__ float g_d3b[BB*CC*NN];
__device__ float g_o1[BB*CC*NN];
__device__ float g_o2[BB*CC*NN];

// ---------------- 1x1 conv as GEMM: Y[b,o,n] = sum_c W[o,c]*X[b,c,n] + bias[o] ----
// grid: (NN/64, ceil(O/64), B), block 256
__global__ void gemm1x1_kernel(const float* __restrict__ W, const float* __restrict__ bias,
                               const float* __restrict__ X, float* __restrict__ Y, int O)
{
    const int n0 = blockIdx.x * 64;
    const int o0 = blockIdx.y * 64;
    const int b  = blockIdx.z;

    __shared__ float Ws[16][64];
    __shared__ float Xs[16][64];

    const int tx = threadIdx.x & 15;   // n dir
    const int ty = threadIdx.x >> 4;   // o dir

    float acc[4][4];
#pragma unroll
    for (int m = 0; m < 4; m++)
#pragma unroll
        for (int n = 0; n < 4; n++) acc[m][n] = 0.f;

    const float* Xb = X + (size_t)b * CC * NN;

    for (int k0 = 0; k0 < CC; k0 += 16) {
#pragma unroll
        for (int i = 0; i < 4; i++) {
            int idx = threadIdx.x + i * 256;
            int e  = idx & 63;
            int kc = idx >> 6;
            float wv = 0.f;
            if (o0 + e < O) wv = W[(size_t)(o0 + e) * CC + k0 + kc];
            Ws[kc][e] = wv;
            Xs[kc][e] = Xb[(size_t)(k0 + kc) * NN + n0 + e];
        }
        __syncthreads();
#pragma unroll
        for (int kc = 0; kc < 16; kc++) {
            float a[4], bv[4];
#pragma unroll
            for (int m = 0; m < 4; m++) a[m] = Ws[kc][ty * 4 + m];
#pragma unroll
            for (int n = 0; n < 4; n++) bv[n] = Xs[kc][tx * 4 + n];
#pragma unroll
            for (int m = 0; m < 4; m++)
#pragma unroll
                for (int n = 0; n < 4; n++) acc[m][n] += a[m] * bv[n];
        }
        __syncthreads();
    }

#pragma unroll
    for (int m = 0; m < 4; m++) {
        int o = o0 + ty * 4 + m;
        if (o < O) {
            float bo = bias[o];
#pragma unroll
            for (int n = 0; n < 4; n++)
                Y[((size_t)b * O + o) * NN + n0 + tx * 4 + n] = acc[m][n] + bo;
        }
    }
}

// ---------------- direct 3x3 conv (SAME, zero pad) -------------------------------
// grid: (CC/64, HH, B), block 256. Out tile = 64 o x 64 w (one image row).
__global__ void conv3x3_kernel(const float* __restrict__ W3, const float* __restrict__ bias,
                               const float* __restrict__ X, float* __restrict__ Y)
{
    const int o0 = blockIdx.x * 64;
    const int h  = blockIdx.y;
    const int b  = blockIdx.z;

    __shared__ float Ws[8][9][64];   // [c][ky*3+kx][o]
    __shared__ float Xs[8][3][72];   // [c][ky][w+1], halo padded

    const int tx = threadIdx.x & 15;
    const int ty = threadIdx.x >> 4;

    float acc[4][4];
#pragma unroll
    for (int m = 0; m < 4; m++)
#pragma unroll
        for (int n = 0; n < 4; n++) acc[m][n] = 0.f;

    const float* Xb = X + (size_t)b * CC * NN;

    for (int c0 = 0; c0 < CC; c0 += 8) {
        for (int idx = threadIdx.x; idx < 8 * 3 * 72; idx += 256) {
            int kc = idx / (3 * 72);
            int r  = (idx / 72) % 3;
            int wc = idx % 72;
            float v = 0.f;
            int hh = h + r - 1;
            int ww = wc - 1;
            if (hh >= 0 && hh < HH && ww >= 0 && ww < WW)
                v = Xb[(size_t)(c0 + kc) * NN + hh * WW + ww];
            Xs[kc][r][wc] = v;
        }
        for (int idx = threadIdx.x; idx < 8 * 9 * 64; idx += 256) {
            int o  = idx & 63;
            int k9 = (idx >> 6) % 9;
            int kc = idx / (64 * 9);
            Ws[kc][k9][o] = W3[((size_t)(o0 + o) * CC + c0 + kc) * 9 + k9];
        }
        __syncthreads();
#pragma unroll
        for (int kc = 0; kc < 8; kc++) {
#pragma unroll
            for (int r = 0; r < 3; r++) {
                float xv[6];
#pragma unroll
                for (int n = 0; n < 6; n++) xv[n] = Xs[kc][r][tx * 4 + n];
#pragma unroll
                for (int kx = 0; kx < 3; kx++) {
                    float wv[4];
#pragma unroll
                    for (int m = 0; m < 4; m++) wv[m] = Ws[kc][r * 3 + kx][ty * 4 + m];
#pragma unroll
                    for (int m = 0; m < 4; m++)
#pragma unroll
                        for (int n = 0; n < 4; n++)
                            acc[m][n] += wv[m] * xv[n + kx];
                }
            }
        }
        __syncthreads();
    }

#pragma unroll
    for (int m = 0; m < 4; m++) {
        int o = o0 + ty * 4 + m;
        float bo = bias[o];
#pragma unroll
        for (int n = 0; n < 4; n++)
            Y[((size_t)b * CC + o) * NN + h * WW + tx * 4 + n] = acc[m][n] + bo;
    }
}

// ---------------- flash attention ------------------------------------------------
// Q,K: (B,32,N) d-major; V,O: (B,256,N) c-major.
// S[i,j] = sum_d Q[d,i]*K[d,j]; P = softmax_j(S); O[c,i] = sum_j P[i,j]*V[c,j]
// grid: (N/64, B), block 256, dynamic smem ~100 KB
#define FA_SMEM_FLOATS (64*33 + 64*33 + 64*65 + 64*257 + 64*3)

__global__ void flashattn_kernel(const float* __restrict__ Q, const float* __restrict__ K,
                                 const float* __restrict__ V, float* __restrict__ O)
{
    extern __shared__ float fsm[];
    float* Qs   = fsm;                 // [64][33]
    float* Ks   = Qs + 64 * 33;        // [64][33]
    float* Ss   = Ks + 64 * 33;        // [64][65]
    float* Vt   = Ss + 64 * 65;        // [64][257]
    float* mrow = Vt + 64 * 257;       // [64]
    float* lrow = mrow + 64;           // [64]
    float* arow = lrow + 64;           // [64]

    const int i0  = blockIdx.x * 64;
    const int b   = blockIdx.y;
    const int tid = threadIdx.x;

    const float* Qb = Q + (size_t)b * CKD * NN;
    const float* Kb = K + (size_t)b * CKD * NN;
    const float* Vb = V + (size_t)b * CC * NN;

    // load Q tile (transposed into [i][d])
    for (int idx = tid; idx < 64 * CKD; idx += 256) {
        int i = idx & 63;
        int d = idx >> 6;
        Qs[i * 33 + d] = Qb[(size_t)d * NN + i0 + i];
    }
    if (tid < 64) { mrow[tid] = -1e30f; lrow[tid] = 0.f; }

    float acc[4][16];
#pragma unroll
    for (int m = 0; m < 4; m++)
#pragma unroll
        for (int n = 0; n < 16; n++) acc[m][n] = 0.f;

    const int txS = tid & 15, tyS = tid >> 4;   // S tile mapping
    const int r2  = tid >> 2, q2 = tid & 3;     // softmax: row, quarter
    const int tx3 = tid & 15, ty3 = tid >> 4;   // PV: i = ty3*4+m, c = tx3 + 16n

    __syncthreads();

    for (int j0 = 0; j0 < NN; j0 += 64) {
        // load K tile
        for (int idx = tid; idx < 64 * CKD; idx += 256) {
            int j = idx & 63;
            int d = idx >> 6;
            Ks[j * 33 + d] = Kb[(size_t)d * NN + j0 + j];
        }
        // load V tile transposed [j][c]
        for (int idx = tid; idx < 64 * CC; idx += 256) {
            int j = idx & 63;
            int c = idx >> 6;
            Vt[j * 257 + c] = Vb[(size_t)c * NN + j0 + j];
        }
        __syncthreads();

        // S = Q K^T
        float s[4][4];
#pragma unroll
        for (int m = 0; m < 4; m++)
#pragma unroll
            for (int n = 0; n < 4; n++) s[m][n] = 0.f;
#pragma unroll
        for (int d = 0; d < CKD; d++) {
            float a[4], bv[4];
#pragma unroll
            for (int m = 0; m < 4; m++) a[m]  = Qs[(tyS * 4 + m) * 33 + d];
#pragma unroll
            for (int n = 0; n < 4; n++) bv[n] = Ks[(txS * 4 + n) * 33 + d];
#pragma unroll
            for (int m = 0; m < 4; m++)
#pragma unroll
                for (int n = 0; n < 4; n++) s[m][n] += a[m] * bv[n];
        }
#pragma unroll
        for (int m = 0; m < 4; m++)
#pragma unroll
            for (int n = 0; n < 4; n++)
                Ss[(tyS * 4 + m) * 65 + txS * 4 + n] = s[m][n];
        __syncthreads();

        // online softmax: 4 lanes per row (consecutive lanes in a warp)
        float tmax = -1e30f;
        for (int jj = q2 * 16; jj < q2 * 16 + 16; jj++)
            tmax = fmaxf(tmax, Ss[r2 * 65 + jj]);
        tmax = fmaxf(tmax, __shfl_xor_sync(0xffffffffu, tmax, 1));
        tmax = fmaxf(tmax, __shfl_xor_sync(0xffffffffu, tmax, 2));
        float mold = mrow[r2];
        float mnew = fmaxf(mold, tmax);
        float alpha = __expf(mold - mnew);
        if (q2 == 0) { mrow[r2] = mnew; arow[r2] = alpha; }

        float tsum = 0.f;
        for (int jj = q2 * 16; jj < q2 * 16 + 16; jj++) {
            float p = __expf(Ss[r2 * 65 + jj] - mnew);
            Ss[r2 * 65 + jj] = p;
            tsum += p;
        }
        tsum += __shfl_xor_sync(0xffffffffu, tsum, 1);
        tsum += __shfl_xor_sync(0xffffffffu, tsum, 2);
        if (q2 == 0) lrow[r2] = lrow[r2] * alpha + tsum;
        __syncthreads();

        // rescale accumulators, then O += P * V
#pragma unroll
        for (int m = 0; m < 4; m++) {
            float al = arow[ty3 * 4 + m];
#pragma unroll
            for (int n = 0; n < 16; n++) acc[m][n] *= al;
        }
        for (int j = 0; j < 64; j++) {
            float p[4];
#pragma unroll
            for (int m = 0; m < 4; m++) p[m] = Ss[(ty3 * 4 + m) * 65 + j];
#pragma unroll
            for (int n = 0; n < 16; n++) {
                float vv = Vt[j * 257 + tx3 + 16 * n];
#pragma unroll
                for (int m = 0; m < 4; m++) acc[m][n] += p[m] * vv;
            }
        }
        __syncthreads();
    }

    // normalize and write (staged through smem for coalesced stores)
    float linv[4];
#pragma unroll
    for (int m = 0; m < 4; m++) linv[m] = 1.f / lrow[ty3 * 4 + m];

    for (int cb = 0; cb < 4; cb++) {
        __syncthreads();
#pragma unroll
        for (int nn = 0; nn < 4; nn++) {
            int cl = tx3 + 16 * nn;            // 0..63 within this chunk
#pragma unroll
            for (int m = 0; m < 4; m++)
                Vt[cl * 68 + ty3 * 4 + m] = acc[m][cb * 4 + nn] * linv[m];
        }
        __syncthreads();
        for (int idx = tid; idx < 64 * 64; idx += 256) {
            int cl = idx >> 6;
            int i  = idx & 63;
            O[((size_t)b * CC + cb * 64 + cl) * NN + i0 + i] = Vt[cl * 68 + i];
        }
    }
}

// ---------------- combine: out = x + gamma*(attn + d1 + d3) ----------------------
__global__ void combine_kernel(const float* __restrict__ x, const float* __restrict__ o,
                               const float* __restrict__ d1, const float* __restrict__ d3,
                               const float* __restrict__ gamma, float* __restrict__ out,
                               int total4)
{
    int i = blockIdx.x * blockDim.x + threadIdx.x;
    float g = gamma[0];
    if (i < total4) {
        float4 xv = ((const float4*)x)[i];
        float4 ov = ((const float4*)o)[i];
        float4 dv = ((const float4*)d1)[i];
        float4 ev = ((const float4*)d3)[i];
        float4 r;
        r.x = xv.x + g * (ov.x + dv.x + ev.x);
        r.y = xv.y + g * (ov.y + dv.y + ev.y);
        r.z = xv.z + g * (ov.z + dv.z + ev.z);
        r.w = xv.w + g * (ov.w + dv.w + ev.w);
        ((float4*)out)[i] = r;
    }
}

// ---------------- host launcher --------------------------------------------------
extern "C" void kernel_launch(void* const* d_in, const int* in_sizes, int n_in,
                              void* d_out, int out_size)
{
    (void)in_sizes; (void)n_in; (void)out_size;

    const float* x1  = (const float*)d_in[0];
    const float* x2  = (const float*)d_in[1];
    const float* wq1 = (const float*)d_in[2];
    const float* bq1 = (const float*)d_in[3];
    const float* wk1 = (const float*)d_in[4];
    const float* bk1 = (const float*)d_in[5];
    const float* wv1 = (const float*)d_in[6];
    const float* bv1 = (const float*)d_in[7];
    const float* wq2 = (const float*)d_in[8];
    const float* bq2 = (const float*)d_in[9];
    const float* wk2 = (const float*)d_in[10];
    const float* bk2 = (const float*)d_in[11];
    const float* wv2 = (const float*)d_in[12];
    const float* bv2 = (const float*)d_in[13];
    const float* wd1 = (const float*)d_in[14];
    const float* bd1 = (const float*)d_in[15];
    const float* wd3 = (const float*)d_in[16];
    const float* bd3 = (const float*)d_in[17];
    const float* gm1 = (const float*)d_in[18];
    const float* gm2 = (const float*)d_in[19];
    float* out = (float*)d_out;

    float *p_q1, *p_k1, *p_q2, *p_k2, *p_v1, *p_v2;
    float *p_d1a, *p_d1b, *p_d3a, *p_d3b, *p_o1, *p_o2;
    cudaGetSymbolAddress((void**)&p_q1, g_q1);
    cudaGetSymbolAddress((void**)&p_k1, g_k1);
    cudaGetSymbolAddress((void**)&p_q2, g_q2);
    cudaGetSymbolAddress((void**)&p_k2, g_k2);
    cudaGetSymbolAddress((void**)&p_v1, g_v1);
    cudaGetSymbolAddress((void**)&p_v2, g_v2);
    cudaGetSymbolAddress((void**)&p_d1a, g_d1a);
    cudaGetSymbolAddress((void**)&p_d1b, g_d1b);
    cudaGetSymbolAddress((void**)&p_d3a, g_d3a);
    cudaGetSymbolAddress((void**)&p_d3b, g_d3b);
    cudaGetSymbolAddress((void**)&p_o1, g_o1);
    cudaGetSymbolAddress((void**)&p_o2, g_o2);

    // 1x1 projections
    {
        dim3 blk(256);
        dim3 gQK(NN / 64, 1, BB);
        gemm1x1_kernel<<<gQK, blk>>>(wq1, bq1, x1, p_q1, CKD);
        gemm1x1_kernel<<<gQK, blk>>>(wk1, bk1, x1, p_k1, CKD);
        gemm1x1_kernel<<<gQK, blk>>>(wq2, bq2, x2, p_q2, CKD);
        gemm1x1_kernel<<<gQK, blk>>>(wk2, bk2, x2, p_k2, CKD);
        dim3 gV(NN / 64, CC / 64, BB);
        gemm1x1_kernel<<<gV, blk>>>(wv1, bv1, x1, p_v1, CC);
        gemm1x1_kernel<<<gV, blk>>>(wv2, bv2, x2, p_v2, CC);
        gemm1x1_kernel<<<gV, blk>>>(wd1, bd1, x1, p_d1a, CC);
        gemm1x1_kernel<<<gV, blk>>>(wd1, bd1, x2, p_d1b, CC);
    }

    // 3x3 convs
    {
        dim3 blk(256);
        dim3 g(CC / 64, HH, BB);
        conv3x3_kernel<<<g, blk>>>(wd3, bd3, x1, p_d3a);
        conv3x3_kernel<<<g, blk>>>(wd3, bd3, x2, p_d3b);
    }

    // flash attention (dynamic smem > 48KB needs opt-in)
    {
        const size_t smem = (size_t)FA_SMEM_FLOATS * sizeof(float);
        cudaFuncSetAttribute(flashattn_kernel,
                             cudaFuncAttributeMaxDynamicSharedMemorySize, (int)smem);
        dim3 blk(256);
        dim3 g(NN / 64, BB);
        // attn1: queries from x1, keys/values from x2
        flashattn_kernel<<<g, blk, smem>>>(p_q1, p_k2, p_v2, p_o1);
        // attn2: queries from x2, keys/values from x1
        flashattn_kernel<<<g, blk, smem>>>(p_q2, p_k1, p_v1, p_o2);
    }

    // combine + residual
    {
        int total  = BB * CC * NN;
        int total4 = total / 4;
        int threads = 256;
        int blocks = (total4 + threads - 1) / threads;
        combine_kernel<<<blocks, threads>>>(x1, p_o1, p_d1a, p_d3a, gm1, out, total4);
        combine_kernel<<<blocks, threads>>>(x2, p_o2, p_d1b, p_d3b, gm2, out + total, total4);
    }
}

// round 2
// speedup vs baseline: 1.7212x; 1.7212x over previous
#include <cuda_runtime.h>
#include <cstdint>
#include <cstddef>

#define BB 4
#define CC 256
#define CKD 32
#define NN 4096
#define HH 64
#define WW 64

// ---------------- scratch (device globals; no allocation allowed) ----------------
__device__ float g_q1[BB*CKD*NN];
__device__ float g_k1[BB*CKD*NN];
__device__ float g_q2[BB*CKD*NN];
__device__ float g_k2[BB*CKD*NN];
__device__ float g_v1[BB*CC*NN];
__device__ float g_v2[BB*CC*NN];
__device__ float g_d1a[BB*CC*NN];
__device__ float g_d1b[BB*CC*NN];
__device__ float g_d3a[BB*CC*NN];
__device__ float g_d3b[BB*CC*NN];
__device__ float g_o1[BB*CC*NN];
__device__ float g_o2[BB*CC*NN];

// ---------------- tf32 helpers ---------------------------------------------------
__device__ __forceinline__ uint32_t f2tf32(float x) {
    uint32_t u;
    asm("cvt.rna.tf32.f32 %0, %1;" : "=r"(u) : "f"(x));
    return u;
}

__device__ __forceinline__ void mma8(float* c,
                                     uint32_t a0, uint32_t a1, uint32_t a2, uint32_t a3,
                                     uint32_t b0, uint32_t b1) {
    asm volatile(
        "mma.sync.aligned.m16n8k8.row.col.f32.tf32.tf32.f32 "
        "{%0,%1,%2,%3}, {%4,%5,%6,%7}, {%8,%9}, {%0,%1,%2,%3};"
        : "+f"(c[0]), "+f"(c[1]), "+f"(c[2]), "+f"(c[3])
        : "r"(a0), "r"(a1), "r"(a2), "r"(a3), "r"(b0), "r"(b1));
}

// ---------------- 1x1 conv as GEMM: Y[b,o,n] = sum_c W[o,c]*X[b,c,n] + bias[o] ----
__global__ void gemm1x1_kernel(const float* __restrict__ W, const float* __restrict__ bias,
                               const float* __restrict__ X, float* __restrict__ Y, int O)
{
    const int n0 = blockIdx.x * 64;
    const int o0 = blockIdx.y * 64;
    const int b  = blockIdx.z;

    __shared__ float Ws[16][64];
    __shared__ float Xs[16][64];

    const int tx = threadIdx.x & 15;
    const int ty = threadIdx.x >> 4;

    float acc[4][4];
#pragma unroll
    for (int m = 0; m < 4; m++)
#pragma unroll
        for (int n = 0; n < 4; n++) acc[m][n] = 0.f;

    const float* Xb = X + (size_t)b * CC * NN;

    for (int k0 = 0; k0 < CC; k0 += 16) {
#pragma unroll
        for (int i = 0; i < 4; i++) {
            int idx = threadIdx.x + i * 256;
            int e  = idx & 63;
            int kc = idx >> 6;
            float wv = 0.f;
            if (o0 + e < O) wv = W[(size_t)(o0 + e) * CC + k0 + kc];
            Ws[kc][e] = wv;
            Xs[kc][e] = Xb[(size_t)(k0 + kc) * NN + n0 + e];
        }
        __syncthreads();
#pragma unroll
        for (int kc = 0; kc < 16; kc++) {
            float a[4], bv[4];
#pragma unroll
            for (int m = 0; m < 4; m++) a[m] = Ws[kc][ty * 4 + m];
#pragma unroll
            for (int n = 0; n < 4; n++) bv[n] = Xs[kc][tx * 4 + n];
#pragma unroll
            for (int m = 0; m < 4; m++)
#pragma unroll
                for (int n = 0; n < 4; n++) acc[m][n] += a[m] * bv[n];
        }
        __syncthreads();
    }

#pragma unroll
    for (int m = 0; m < 4; m++) {
        int o = o0 + ty * 4 + m;
        if (o < O) {
            float bo = bias[o];
#pragma unroll
            for (int n = 0; n < 4; n++)
                Y[((size_t)b * O + o) * NN + n0 + tx * 4 + n] = acc[m][n] + bo;
        }
    }
}

// ---------------- direct 3x3 conv (SAME, zero pad) -------------------------------
__global__ void conv3x3_kernel(const float* __restrict__ W3, const float* __restrict__ bias,
                               const float* __restrict__ X, float* __restrict__ Y)
{
    const int o0 = blockIdx.x * 64;
    const int h  = blockIdx.y;
    const int b  = blockIdx.z;

    __shared__ float Ws[8][9][64];
    __shared__ float Xs[8][3][72];

    const int tx = threadIdx.x & 15;
    const int ty = threadIdx.x >> 4;

    float acc[4][4];
#pragma unroll
    for (int m = 0; m < 4; m++)
#pragma unroll
        for (int n = 0; n < 4; n++) acc[m][n] = 0.f;

    const float* Xb = X + (size_t)b * CC * NN;

    for (int c0 = 0; c0 < CC; c0 += 8) {
        for (int idx = threadIdx.x; idx < 8 * 3 * 72; idx += 256) {
            int kc = idx / (3 * 72);
            int r  = (idx / 72) % 3;
            int wc = idx % 72;
            float v = 0.f;
            int hh = h + r - 1;
            int ww = wc - 1;
            if (hh >= 0 && hh < HH && ww >= 0 && ww < WW)
                v = Xb[(size_t)(c0 + kc) * NN + hh * WW + ww];
            Xs[kc][r][wc] = v;
        }
        for (int idx = threadIdx.x; idx < 8 * 9 * 64; idx += 256) {
            int o  = idx & 63;
            int k9 = (idx >> 6) % 9;
            int kc = idx / (64 * 9);
            Ws[kc][k9][o] = W3[((size_t)(o0 + o) * CC + c0 + kc) * 9 + k9];
        }
        __syncthreads();
#pragma unroll
        for (int kc = 0; kc < 8; kc++) {
#pragma unroll
            for (int r = 0; r < 3; r++) {
                float xv[6];
#pragma unroll
                for (int n = 0; n < 6; n++) xv[n] = Xs[kc][r][tx * 4 + n];
#pragma unroll
                for (int kx = 0; kx < 3; kx++) {
                    float wv[4];
#pragma unroll
                    for (int m = 0; m < 4; m++) wv[m] = Ws[kc][r * 3 + kx][ty * 4 + m];
#pragma unroll
                    for (int m = 0; m < 4; m++)
#pragma unroll
                        for (int n = 0; n < 4; n++)
                            acc[m][n] += wv[m] * xv[n + kx];
                }
            }
        }
        __syncthreads();
    }

#pragma unroll
    for (int m = 0; m < 4; m++) {
        int o = o0 + ty * 4 + m;
        float bo = bias[o];
#pragma unroll
        for (int n = 0; n < 4; n++)
            Y[((size_t)b * CC + o) * NN + h * WW + tx * 4 + n] = acc[m][n] + bo;
    }
}

// ---------------- flash attention via mma.sync tf32 ------------------------------
// Q,K: (B,32,N) d-major; V,O: (B,256,N) c-major.
// BM=128, BN=64, 512 threads (16 warps). Warp w: m-tiles {2*(w&3), 2*(w&3)+1},
// PV c-range 64*(w>>2). S staged through smem for online softmax.
#define QS_STRIDE 36
#define SS_STRIDE 65
#define VS_STRIDE 72

#define SM_QS 0
#define SM_KS (128 * QS_STRIDE)                 // 4608
#define SM_SS (SM_KS + 64 * QS_STRIDE)          // 6912
#define SM_VS (SM_SS + 128 * SS_STRIDE)         // 15232
#define SM_MR (SM_VS + 256 * VS_STRIDE)         // 33664
#define SM_LR (SM_MR + 128)
#define SM_AR (SM_LR + 128)
#define FA2_SMEM_BYTES ((SM_AR + 128) * 4)      // 136192 B

__global__ __launch_bounds__(512, 1)
void flashattn_mma(const float* __restrict__ Q, const float* __restrict__ K,
                   const float* __restrict__ V, float* __restrict__ O)
{
    extern __shared__ float sm[];
    float* Qs   = sm + SM_QS;
    float* Ks   = sm + SM_KS;
    float* Ss   = sm + SM_SS;
    float* Vs   = sm + SM_VS;
    float* mrow = sm + SM_MR;
    float* lrow = sm + SM_LR;
    float* arow = sm + SM_AR;

    const int tid  = threadIdx.x;
    const int w    = tid >> 5;
    const int lane = tid & 31;
    const int g    = lane >> 2;
    const int qb   = lane & 3;
    const int wm2  = w & 3;     // m-tile pair
    const int wc   = w >> 2;    // c-range / n-pair
    const int i0   = blockIdx.x * 128;
    const int b    = blockIdx.y;

    const float* Qb = Q + (size_t)b * CKD * NN;
    const float* Kb = K + (size_t)b * CKD * NN;
    const float* Vb = V + (size_t)b * CC * NN;

    // load Q tile (128 x 32), transposed to [i][d], stored as tf32 bits
    for (int idx = tid; idx < 128 * CKD; idx += 512) {
        int i = idx & 127, d = idx >> 7;
        Qs[i * QS_STRIDE + d] = __uint_as_float(f2tf32(Qb[(size_t)d * NN + i0 + i]));
    }
    if (tid < 128) { mrow[tid] = -1e30f; lrow[tid] = 0.f; arow[tid] = 1.f; }

    float acc[2][8][4];
#pragma unroll
    for (int mt = 0; mt < 2; mt++)
#pragma unroll
        for (int nt = 0; nt < 8; nt++)
#pragma unroll
            for (int e = 0; e < 4; e++) acc[mt][nt][e] = 0.f;

    const int srow = tid >> 2;   // softmax row 0..127
    const int sq   = tid & 3;    // quarter

    __syncthreads();

    for (int j0 = 0; j0 < NN; j0 += 64) {
        // K tile (64 x 32) -> [j][d] tf32
        for (int idx = tid; idx < 64 * CKD; idx += 512) {
            int j = idx & 63, d = idx >> 6;
            Ks[j * QS_STRIDE + d] = __uint_as_float(f2tf32(Kb[(size_t)d * NN + j0 + j]));
        }
        // V tile (256 c x 64 j) -> [c][j] tf32
        for (int idx = tid; idx < CC * 64; idx += 512) {
            int j = idx & 63, c = idx >> 6;
            Vs[c * VS_STRIDE + j] = __uint_as_float(f2tf32(Vb[(size_t)c * NN + j0 + j]));
        }
        __syncthreads();

        // ---- S = Q K^T (each warp: 2 m-tiles x 2 n-tiles) ----
        float s[2][2][4];
#pragma unroll
        for (int mt = 0; mt < 2; mt++)
#pragma unroll
            for (int nt = 0; nt < 2; nt++)
#pragma unroll
                for (int e = 0; e < 4; e++) s[mt][nt][e] = 0.f;

#pragma unroll
        for (int k = 0; k < 4; k++) {
            const int d0 = 8 * k;
            uint32_t a[2][4];
#pragma unroll
            for (int mt = 0; mt < 2; mt++) {
                const int br = 16 * (2 * wm2 + mt);
                a[mt][0] = __float_as_uint(Qs[(br + g) * QS_STRIDE + d0 + qb]);
                a[mt][1] = __float_as_uint(Qs[(br + g + 8) * QS_STRIDE + d0 + qb]);
                a[mt][2] = __float_as_uint(Qs[(br + g) * QS_STRIDE + d0 + qb + 4]);
                a[mt][3] = __float_as_uint(Qs[(br + g + 8) * QS_STRIDE + d0 + qb + 4]);
            }
            uint32_t bb[2][2];
#pragma unroll
            for (int nt = 0; nt < 2; nt++) {
                const int jb = 8 * (2 * wc + nt);
                bb[nt][0] = __float_as_uint(Ks[(jb + g) * QS_STRIDE + d0 + qb]);
                bb[nt][1] = __float_as_uint(Ks[(jb + g) * QS_STRIDE + d0 + qb + 4]);
            }
#pragma unroll
            for (int mt = 0; mt < 2; mt++)
#pragma unroll
                for (int nt = 0; nt < 2; nt++)
                    mma8(s[mt][nt], a[mt][0], a[mt][1], a[mt][2], a[mt][3],
                         bb[nt][0], bb[nt][1]);
        }

#pragma unroll
        for (int mt = 0; mt < 2; mt++)
#pragma unroll
            for (int nt = 0; nt < 2; nt++) {
                const int rr = 16 * (2 * wm2 + mt) + g;
                const int cb = 8 * (2 * wc + nt) + 2 * qb;
                Ss[rr * SS_STRIDE + cb]           = s[mt][nt][0];
                Ss[rr * SS_STRIDE + cb + 1]       = s[mt][nt][1];
                Ss[(rr + 8) * SS_STRIDE + cb]     = s[mt][nt][2];
                Ss[(rr + 8) * SS_STRIDE + cb + 1] = s[mt][nt][3];
            }
        __syncthreads();

        // ---- online softmax (4 lanes per row, 16 cols each) ----
        {
            float tmax = -1e30f;
#pragma unroll
            for (int jj = sq * 16; jj < sq * 16 + 16; jj++)
                tmax = fmaxf(tmax, Ss[srow * SS_STRIDE + jj]);
            tmax = fmaxf(tmax, __shfl_xor_sync(0xffffffffu, tmax, 1));
            tmax = fmaxf(tmax, __shfl_xor_sync(0xffffffffu, tmax, 2));
            float mold = mrow[srow];
            float mnew = fmaxf(mold, tmax);
            float tsum = 0.f;
#pragma unroll
            for (int jj = sq * 16; jj < sq * 16 + 16; jj++) {
                float p = __expf(Ss[srow * SS_STRIDE + jj] - mnew);
                Ss[srow * SS_STRIDE + jj] = __uint_as_float(f2tf32(p));
                tsum += p;
            }
            tsum += __shfl_xor_sync(0xffffffffu, tsum, 1);
            tsum += __shfl_xor_sync(0xffffffffu, tsum, 2);
            if (sq == 0) {
                float alpha = __expf(mold - mnew);
                mrow[srow] = mnew;
                arow[srow] = alpha;
                lrow[srow] = lrow[srow] * alpha + tsum;
            }
        }
        __syncthreads();

        // ---- rescale accumulators ----
#pragma unroll
        for (int mt = 0; mt < 2; mt++) {
            const int br = 16 * (2 * wm2 + mt);
            float alo = arow[br + g];
            float ahi = arow[br + g + 8];
#pragma unroll
            for (int nt = 0; nt < 8; nt++) {
                acc[mt][nt][0] *= alo;
                acc[mt][nt][1] *= alo;
                acc[mt][nt][2] *= ahi;
                acc[mt][nt][3] *= ahi;
            }
        }

        // ---- O += P V (each warp: 2 m-tiles x 8 n-tiles, k = 64) ----
#pragma unroll
        for (int k = 0; k < 8; k++) {
            const int jk = 8 * k;
            uint32_t a[2][4];
#pragma unroll
            for (int mt = 0; mt < 2; mt++) {
                const int br = 16 * (2 * wm2 + mt);
                a[mt][0] = __float_as_uint(Ss[(br + g) * SS_STRIDE + jk + qb]);
                a[mt][1] = __float_as_uint(Ss[(br + g + 8) * SS_STRIDE + jk + qb]);
                a[mt][2] = __float_as_uint(Ss[(br + g) * SS_STRIDE + jk + qb + 4]);
                a[mt][3] = __float_as_uint(Ss[(br + g + 8) * SS_STRIDE + jk + qb + 4]);
            }
#pragma unroll
            for (int nt = 0; nt < 8; nt++) {
                const int c0 = 64 * wc + 8 * nt;
                uint32_t b0 = __float_as_uint(Vs[(c0 + g) * VS_STRIDE + jk + qb]);
                uint32_t b1 = __float_as_uint(Vs[(c0 + g) * VS_STRIDE + jk + qb + 4]);
                mma8(acc[0][nt], a[0][0], a[0][1], a[0][2], a[0][3], b0, b1);
                mma8(acc[1][nt], a[1][0], a[1][1], a[1][2], a[1][3], b0, b1);
            }
        }
        __syncthreads();
    }

    // ---- epilogue: normalize, stage via smem, coalesced store ----
    float linv[2][2];
#pragma unroll
    for (int mt = 0; mt < 2; mt++) {
        const int br = 16 * (2 * wm2 + mt);
        linv[mt][0] = 1.f / lrow[br + g];
        linv[mt][1] = 1.f / lrow[br + g + 8];
    }
    float* smO = Vs;  // reuse; needs 128*132 = 16896 <= 18432

    for (int p = 0; p < 2; p++) {
        __syncthreads();
        if ((wc >> 1) == p) {
#pragma unroll
            for (int mt = 0; mt < 2; mt++)
#pragma unroll
                for (int nt = 0; nt < 8; nt++) {
                    const int rr = 16 * (2 * wm2 + mt) + g;
                    const int cl = 64 * wc + 8 * nt + 2 * qb - 128 * p;
                    smO[cl * 132 + rr]           = acc[mt][nt][0] * linv[mt][0];
                    smO[(cl + 1) * 132 + rr]     = acc[mt][nt][1] * linv[mt][0];
                    smO[cl * 132 + rr + 8]       = acc[mt][nt][2] * linv[mt][1];
                    smO[(cl + 1) * 132 + rr + 8] = acc[mt][nt][3] * linv[mt][1];
                }
        }
        __syncthreads();
        for (int idx = tid; idx < 128 * 32; idx += 512) {
            int c = idx >> 5, i4 = idx & 31;
            float4 v = *reinterpret_cast<float4*>(smO + c * 132 + i4 * 4);
            *reinterpret_cast<float4*>(
                O + ((size_t)(b * CC + 128 * p + c)) * NN + i0 + i4 * 4) = v;
        }
    }
}

// ---------------- combine: out = x + gamma*(attn + d1 + d3) ----------------------
__global__ void combine_kernel(const float* __restrict__ x, const float* __restrict__ o,
                               const float* __restrict__ d1, const float* __restrict__ d3,
                               const float* __restrict__ gamma, float* __restrict__ out,
                               int total4)
{
    int i = blockIdx.x * blockDim.x + threadIdx.x;
    float g = gamma[0];
    if (i < total4) {
        float4 xv = ((const float4*)x)[i];
        float4 ov = ((const float4*)o)[i];
        float4 dv = ((const float4*)d1)[i];
        float4 ev = ((const float4*)d3)[i];
        float4 r;
        r.x = xv.x + g * (ov.x + dv.x + ev.x);
        r.y = xv.y + g * (ov.y + dv.y + ev.y);
        r.z = xv.z + g * (ov.z + dv.z + ev.z);
        r.w = xv.w + g * (ov.w + dv.w + ev.w);
        ((float4*)out)[i] = r;
    }
}

// ---------------- host launcher --------------------------------------------------
extern "C" void kernel_launch(void* const* d_in, const int* in_sizes, int n_in,
                              void* d_out, int out_size)
{
    (void)in_sizes; (void)n_in; (void)out_size;

    const float* x1  = (const float*)d_in[0];
    const float* x2  = (const float*)d_in[1];
    const float* wq1 = (const float*)d_in[2];
    const float* bq1 = (const float*)d_in[3];
    const float* wk1 = (const float*)d_in[4];
    const float* bk1 = (const float*)d_in[5];
    const float* wv1 = (const float*)d_in[6];
    const float* bv1 = (const float*)d_in[7];
    const float* wq2 = (const float*)d_in[8];
    const float* bq2 = (const float*)d_in[9];
    const float* wk2 = (const float*)d_in[10];
    const float* bk2 = (const float*)d_in[11];
    const float* wv2 = (const float*)d_in[12];
    const float* bv2 = (const float*)d_in[13];
    const float* wd1 = (const float*)d_in[14];
    const float* bd1 = (const float*)d_in[15];
    const float* wd3 = (const float*)d_in[16];
    const float* bd3 = (const float*)d_in[17];
    const float* gm1 = (const float*)d_in[18];
    const float* gm2 = (const float*)d_in[19];
    float* out = (float*)d_out;

    float *p_q1, *p_k1, *p_q2, *p_k2, *p_v1, *p_v2;
    float *p_d1a, *p_d1b, *p_d3a, *p_d3b, *p_o1, *p_o2;
    cudaGetSymbolAddress((void**)&p_q1, g_q1);
    cudaGetSymbolAddress((void**)&p_k1, g_k1);
    cudaGetSymbolAddress((void**)&p_q2, g_q2);
    cudaGetSymbolAddress((void**)&p_k2, g_k2);
    cudaGetSymbolAddress((void**)&p_v1, g_v1);
    cudaGetSymbolAddress((void**)&p_v2, g_v2);
    cudaGetSymbolAddress((void**)&p_d1a, g_d1a);
    cudaGetSymbolAddress((void**)&p_d1b, g_d1b);
    cudaGetSymbolAddress((void**)&p_d3a, g_d3a);
    cudaGetSymbolAddress((void**)&p_d3b, g_d3b);
    cudaGetSymbolAddress((void**)&p_o1, g_o1);
    cudaGetSymbolAddress((void**)&p_o2, g_o2);

    // 1x1 projections
    {
        dim3 blk(256);
        dim3 gQK(NN / 64, 1, BB);
        gemm1x1_kernel<<<gQK, blk>>>(wq1, bq1, x1, p_q1, CKD);
        gemm1x1_kernel<<<gQK, blk>>>(wk1, bk1, x1, p_k1, CKD);
        gemm1x1_kernel<<<gQK, blk>>>(wq2, bq2, x2, p_q2, CKD);
        gemm1x1_kernel<<<gQK, blk>>>(wk2, bk2, x2, p_k2, CKD);
        dim3 gV(NN / 64, CC / 64, BB);
        gemm1x1_kernel<<<gV, blk>>>(wv1, bv1, x1, p_v1, CC);
        gemm1x1_kernel<<<gV, blk>>>(wv2, bv2, x2, p_v2, CC);
        gemm1x1_kernel<<<gV, blk>>>(wd1, bd1, x1, p_d1a, CC);
        gemm1x1_kernel<<<gV, blk>>>(wd1, bd1, x2, p_d1b, CC);
    }

    // 3x3 convs
    {
        dim3 blk(256);
        dim3 g(CC / 64, HH, BB);
        conv3x3_kernel<<<g, blk>>>(wd3, bd3, x1, p_d3a);
        conv3x3_kernel<<<g, blk>>>(wd3, bd3, x2, p_d3b);
    }

    // flash attention (tf32 mma)
    {
        cudaFuncSetAttribute(flashattn_mma,
                             cudaFuncAttributeMaxDynamicSharedMemorySize, FA2_SMEM_BYTES);
        dim3 blk(512);
        dim3 g(NN / 128, BB);
        flashattn_mma<<<g, blk, FA2_SMEM_BYTES>>>(p_q1, p_k2, p_v2, p_o1);
        flashattn_mma<<<g, blk, FA2_SMEM_BYTES>>>(p_q2, p_k1, p_v1, p_o2);
    }

    // combine + residual
    {
        int total  = BB * CC * NN;
        int total4 = total / 4;
        int threads = 256;
        int blocks = (total4 + threads - 1) / threads;
        combine_kernel<<<blocks, threads>>>(x1, p_o1, p_d1a, p_d3a, gm1, out, total4);
        combine_kernel<<<blocks, threads>>>(x2, p_o2, p_d1b, p_d3b, gm2, out + total, total4);
    }
}

// round 3
// speedup vs baseline: 1.7994x; 1.0455x over previous
#include <cuda_runtime.h>
#include <cstdint>
#include <cstddef>

#define BB 4
#define CC 256
#define CKD 32
#define NN 4096
#define HH 64
#define WW 64

// ---------------- scratch (device globals; no allocation allowed) ----------------
__device__ float g_q1[BB*CKD*NN];
__device__ float g_k1[BB*CKD*NN];
__device__ float g_q2[BB*CKD*NN];
__device__ float g_k2[BB*CKD*NN];
__device__ float g_v1[BB*CC*NN];
__device__ float g_v2[BB*CC*NN];
__device__ float g_d1a[BB*CC*NN];
__device__ float g_d1b[BB*CC*NN];
__device__ float g_d3a[BB*CC*NN];
__device__ float g_d3b[BB*CC*NN];
__device__ float g_o1[BB*CC*NN];
__device__ float g_o2[BB*CC*NN];

// ---------------- tf32 helpers ---------------------------------------------------
__device__ __forceinline__ uint32_t f2tf32(float x) {
    uint32_t u;
    asm("cvt.rna.tf32.f32 %0, %1;" : "=r"(u) : "f"(x));
    return u;
}

__device__ __forceinline__ void mma8(float* c,
                                     uint32_t a0, uint32_t a1, uint32_t a2, uint32_t a3,
                                     uint32_t b0, uint32_t b1) {
    asm volatile(
        "mma.sync.aligned.m16n8k8.row.col.f32.tf32.tf32.f32 "
        "{%0,%1,%2,%3}, {%4,%5,%6,%7}, {%8,%9}, {%0,%1,%2,%3};"
        : "+f"(c[0]), "+f"(c[1]), "+f"(c[2]), "+f"(c[3])
        : "r"(a0), "r"(a1), "r"(a2), "r"(a3), "r"(b0), "r"(b1));
}

// ---------------- 1x1 conv as GEMM: Y[b,o,n] = sum_c W[o,c]*X[b,c,n] + bias[o] ----
__global__ void gemm1x1_kernel(const float* __restrict__ W, const float* __restrict__ bias,
                               const float* __restrict__ X, float* __restrict__ Y, int O)
{
    const int n0 = blockIdx.x * 64;
    const int o0 = blockIdx.y * 64;
    const int b  = blockIdx.z;

    __shared__ float Ws[16][64];
    __shared__ float Xs[16][64];

    const int tx = threadIdx.x & 15;
    const int ty = threadIdx.x >> 4;

    float acc[4][4];
#pragma unroll
    for (int m = 0; m < 4; m++)
#pragma unroll
        for (int n = 0; n < 4; n++) acc[m][n] = 0.f;

    const float* Xb = X + (size_t)b * CC * NN;

    for (int k0 = 0; k0 < CC; k0 += 16) {
#pragma unroll
        for (int i = 0; i < 4; i++) {
            int idx = threadIdx.x + i * 256;
            int e  = idx & 63;
            int kc = idx >> 6;
            float wv = 0.f;
            if (o0 + e < O) wv = W[(size_t)(o0 + e) * CC + k0 + kc];
            Ws[kc][e] = wv;
            Xs[kc][e] = Xb[(size_t)(k0 + kc) * NN + n0 + e];
        }
        __syncthreads();
#pragma unroll
        for (int kc = 0; kc < 16; kc++) {
            float a[4], bv[4];
#pragma unroll
            for (int m = 0; m < 4; m++) a[m] = Ws[kc][ty * 4 + m];
#pragma unroll
            for (int n = 0; n < 4; n++) bv[n] = Xs[kc][tx * 4 + n];
#pragma unroll
            for (int m = 0; m < 4; m++)
#pragma unroll
                for (int n = 0; n < 4; n++) acc[m][n] += a[m] * bv[n];
        }
        __syncthreads();
    }

#pragma unroll
    for (int m = 0; m < 4; m++) {
        int o = o0 + ty * 4 + m;
        if (o < O) {
            float bo = bias[o];
#pragma unroll
            for (int n = 0; n < 4; n++)
                Y[((size_t)b * O + o) * NN + n0 + tx * 4 + n] = acc[m][n] + bo;
        }
    }
}

// ---------------- direct 3x3 conv (SAME, zero pad) -------------------------------
__global__ void conv3x3_kernel(const float* __restrict__ W3, const float* __restrict__ bias,
                               const float* __restrict__ X, float* __restrict__ Y)
{
    const int o0 = blockIdx.x * 64;
    const int h  = blockIdx.y;
    const int b  = blockIdx.z;

    __shared__ float Ws[8][9][64];
    __shared__ float Xs[8][3][72];

    const int tx = threadIdx.x & 15;
    const int ty = threadIdx.x >> 4;

    float acc[4][4];
#pragma unroll
    for (int m = 0; m < 4; m++)
#pragma unroll
        for (int n = 0; n < 4; n++) acc[m][n] = 0.f;

    const float* Xb = X + (size_t)b * CC * NN;

    for (int c0 = 0; c0 < CC; c0 += 8) {
        for (int idx = threadIdx.x; idx < 8 * 3 * 72; idx += 256) {
            int kc = idx / (3 * 72);
            int r  = (idx / 72) % 3;
            int wc = idx % 72;
            float v = 0.f;
            int hh = h + r - 1;
            int ww = wc - 1;
            if (hh >= 0 && hh < HH && ww >= 0 && ww < WW)
                v = Xb[(size_t)(c0 + kc) * NN + hh * WW + ww];
            Xs[kc][r][wc] = v;
        }
        for (int idx = threadIdx.x; idx < 8 * 9 * 64; idx += 256) {
            int o  = idx & 63;
            int k9 = (idx >> 6) % 9;
            int kc = idx / (64 * 9);
            Ws[kc][k9][o] = W3[((size_t)(o0 + o) * CC + c0 + kc) * 9 + k9];
        }
        __syncthreads();
#pragma unroll
        for (int kc = 0; kc < 8; kc++) {
#pragma unroll
            for (int r = 0; r < 3; r++) {
                float xv[6];
#pragma unroll
                for (int n = 0; n < 6; n++) xv[n] = Xs[kc][r][tx * 4 + n];
#pragma unroll
                for (int kx = 0; kx < 3; kx++) {
                    float wv[4];
#pragma unroll
                    for (int m = 0; m < 4; m++) wv[m] = Ws[kc][r * 3 + kx][ty * 4 + m];
#pragma unroll
                    for (int m = 0; m < 4; m++)
#pragma unroll
                        for (int n = 0; n < 4; n++)
                            acc[m][n] += wv[m] * xv[n + kx];
                }
            }
        }
        __syncthreads();
    }

#pragma unroll
    for (int m = 0; m < 4; m++) {
        int o = o0 + ty * 4 + m;
        float bo = bias[o];
#pragma unroll
        for (int n = 0; n < 4; n++)
            Y[((size_t)b * CC + o) * NN + h * WW + tx * 4 + n] = acc[m][n] + bo;
    }
}

// ---------------- flash attention, register-resident S/P -------------------------
// BM=128, BN=64, 512 threads (16 warps) = 8 m-groups x 2 c-halves.
// Each warp: rows 16*wm..16*wm+15, full j range (softmax entirely in registers),
// PV c-range 128*cw..128*cw+127. QK computed redundantly by the 2 c-half warps.
#define KQ_STRIDE 36
#define V_STRIDE  68

#define SM3_QS 0
#define SM3_KS (128 * KQ_STRIDE)                 // 4608
#define SM3_VS (SM3_KS + 64 * KQ_STRIDE)         // 6912
#define FA3_SMEM_FLOATS (SM3_VS + 256 * V_STRIDE)  // 24320
#define FA3_SMEM_BYTES (FA3_SMEM_FLOATS * 4)       // 97280

__global__ __launch_bounds__(512, 1)
void flashattn_mma(const float* __restrict__ Q, const float* __restrict__ K,
                   const float* __restrict__ V, float* __restrict__ O)
{
    extern __shared__ float sm[];
    float* Qs = sm + SM3_QS;   // [128][36] tf32 bits, [i][d]
    float* Ks = sm + SM3_KS;   // [64][36]  tf32 bits, [j][d]
    float* Vs = sm + SM3_VS;   // [256][68] tf32 bits, [c][j]

    const int tid  = threadIdx.x;
    const int w    = tid >> 5;
    const int lane = tid & 31;
    const int g    = lane >> 2;
    const int qb   = lane & 3;
    const int wm   = w & 7;     // m-group (16 rows)
    const int cw   = w >> 3;    // c half
    const int i0   = blockIdx.x * 128;
    const int b    = blockIdx.y;
    const bool odd = qb & 1;
    const int srcA = (lane & ~3) | (qb >> 1);
    const int srcB = srcA + 2;

    const float* Qb = Q + (size_t)b * CKD * NN;
    const float* Kb = K + (size_t)b * CKD * NN;
    const float* Vb = V + (size_t)b * CC * NN;

    // load Q tile (128 x 32) transposed -> [i][d] tf32 bits
    for (int idx = tid; idx < 128 * CKD; idx += 512) {
        int i = idx & 127, d = idx >> 7;
        Qs[i * KQ_STRIDE + d] = __uint_as_float(f2tf32(Qb[(size_t)d * NN + i0 + i]));
    }
    __syncthreads();

    // hoist Q fragments to registers (rows 16*wm + g/g+8, k=32)
    uint32_t aq[4][4];
#pragma unroll
    for (int kk = 0; kk < 4; kk++) {
        const int d0 = 8 * kk;
        const int br = 16 * wm;
        aq[kk][0] = __float_as_uint(Qs[(br + g) * KQ_STRIDE + d0 + qb]);
        aq[kk][1] = __float_as_uint(Qs[(br + g + 8) * KQ_STRIDE + d0 + qb]);
        aq[kk][2] = __float_as_uint(Qs[(br + g) * KQ_STRIDE + d0 + qb + 4]);
        aq[kk][3] = __float_as_uint(Qs[(br + g + 8) * KQ_STRIDE + d0 + qb + 4]);
    }

    float acc[16][4];
#pragma unroll
    for (int ct = 0; ct < 16; ct++)
#pragma unroll
        for (int e = 0; e < 4; e++) acc[ct][e] = 0.f;

    float mlo = -1e30f, mhi = -1e30f, llo = 0.f, lhi = 0.f;

    for (int j0 = 0; j0 < NN; j0 += 64) {
        __syncthreads();   // protect Ks/Vs from previous iteration's readers
        // K tile (64 x 32) -> [j][d]
        for (int idx = tid; idx < 64 * CKD; idx += 512) {
            int j = idx & 63, d = idx >> 6;
            Ks[j * KQ_STRIDE + d] = __uint_as_float(f2tf32(Kb[(size_t)d * NN + j0 + j]));
        }
        // V tile (256 c x 64 j) -> [c][j]
        for (int idx = tid; idx < CC * 64; idx += 512) {
            int j = idx & 63, c = idx >> 6;
            Vs[c * V_STRIDE + j] = __uint_as_float(f2tf32(Vb[(size_t)c * NN + j0 + j]));
        }
        __syncthreads();

        // ---- S = Q K^T : full 16x64 row-strip per warp, in registers ----
        float s[8][4];
#pragma unroll
        for (int nt = 0; nt < 8; nt++)
#pragma unroll
            for (int e = 0; e < 4; e++) s[nt][e] = 0.f;

#pragma unroll
        for (int kk = 0; kk < 4; kk++) {
            const int d0 = 8 * kk;
#pragma unroll
            for (int nt = 0; nt < 8; nt++) {
                uint32_t b0 = __float_as_uint(Ks[(8 * nt + g) * KQ_STRIDE + d0 + qb]);
                uint32_t b1 = __float_as_uint(Ks[(8 * nt + g) * KQ_STRIDE + d0 + qb + 4]);
                mma8(s[nt], aq[kk][0], aq[kk][1], aq[kk][2], aq[kk][3], b0, b1);
            }
        }

        // ---- online softmax in registers (quad lanes own a full row) ----
        {
            float pmlo = -1e30f, pmhi = -1e30f;
#pragma unroll
            for (int nt = 0; nt < 8; nt++) {
                pmlo = fmaxf(pmlo, fmaxf(s[nt][0], s[nt][1]));
                pmhi = fmaxf(pmhi, fmaxf(s[nt][2], s[nt][3]));
            }
            pmlo = fmaxf(pmlo, __shfl_xor_sync(0xffffffffu, pmlo, 1));
            pmlo = fmaxf(pmlo, __shfl_xor_sync(0xffffffffu, pmlo, 2));
            pmhi = fmaxf(pmhi, __shfl_xor_sync(0xffffffffu, pmhi, 1));
            pmhi = fmaxf(pmhi, __shfl_xor_sync(0xffffffffu, pmhi, 2));

            float mlo_n = fmaxf(mlo, pmlo);
            float mhi_n = fmaxf(mhi, pmhi);
            float alo = __expf(mlo - mlo_n);
            float ahi = __expf(mhi - mhi_n);

            float slo = 0.f, shi = 0.f;
#pragma unroll
            for (int nt = 0; nt < 8; nt++) {
                s[nt][0] = __expf(s[nt][0] - mlo_n);
                s[nt][1] = __expf(s[nt][1] - mlo_n);
                s[nt][2] = __expf(s[nt][2] - mhi_n);
                s[nt][3] = __expf(s[nt][3] - mhi_n);
                slo += s[nt][0] + s[nt][1];
                shi += s[nt][2] + s[nt][3];
            }
            slo += __shfl_xor_sync(0xffffffffu, slo, 1);
            slo += __shfl_xor_sync(0xffffffffu, slo, 2);
            shi += __shfl_xor_sync(0xffffffffu, shi, 1);
            shi += __shfl_xor_sync(0xffffffffu, shi, 2);

            llo = llo * alo + slo;
            lhi = lhi * ahi + shi;
            mlo = mlo_n; mhi = mhi_n;

#pragma unroll
            for (int ct = 0; ct < 16; ct++) {
                acc[ct][0] *= alo; acc[ct][1] *= alo;
                acc[ct][2] *= ahi; acc[ct][3] *= ahi;
            }
        }

        // ---- O += P V : permute C-frag -> A-frag via shuffles, then MMA ----
#pragma unroll
        for (int kk = 0; kk < 8; kk++) {
            float x0 = __shfl_sync(0xffffffffu, s[kk][0], srcA);
            float x1 = __shfl_sync(0xffffffffu, s[kk][1], srcA);
            float y0 = __shfl_sync(0xffffffffu, s[kk][0], srcB);
            float y1 = __shfl_sync(0xffffffffu, s[kk][1], srcB);
            float z0 = __shfl_sync(0xffffffffu, s[kk][2], srcA);
            float z1 = __shfl_sync(0xffffffffu, s[kk][3], srcA);
            float w0 = __shfl_sync(0xffffffffu, s[kk][2], srcB);
            float w1 = __shfl_sync(0xffffffffu, s[kk][3], srcB);
            uint32_t a0 = f2tf32(odd ? x1 : x0);   // (row g,   col qb)
            uint32_t a1 = f2tf32(odd ? z1 : z0);   // (row g+8, col qb)
            uint32_t a2 = f2tf32(odd ? y1 : y0);   // (row g,   col qb+4)
            uint32_t a3 = f2tf32(odd ? w1 : w0);   // (row g+8, col qb+4)

            const int jk = 8 * kk;
#pragma unroll
            for (int ct = 0; ct < 16; ct++) {
                const int c0 = 128 * cw + 8 * ct;
                uint32_t b0 = __float_as_uint(Vs[(c0 + g) * V_STRIDE + jk + qb]);
                uint32_t b1 = __float_as_uint(Vs[(c0 + g) * V_STRIDE + jk + qb + 4]);
                mma8(acc[ct], a0, a1, a2, a3, b0, b1);
            }
        }
    }
    __syncthreads();

    // ---- epilogue: normalize, stage via smem (reuse Vs), coalesced store ----
    const float lilo = 1.f / llo;
    const float lihi = 1.f / lhi;
    float* smO = Vs;   // [128 c][132] needs 16896 <= 17408

    for (int p = 0; p < 2; p++) {
        __syncthreads();
        if (cw == p) {
#pragma unroll
            for (int ct = 0; ct < 16; ct++) {
                const int rr = 16 * wm + g;
                const int cl = 8 * ct + 2 * qb;
                smO[cl * 132 + rr]           = acc[ct][0] * lilo;
                smO[(cl + 1) * 132 + rr]     = acc[ct][1] * lilo;
                smO[cl * 132 + rr + 8]       = acc[ct][2] * lihi;
                smO[(cl + 1) * 132 + rr + 8] = acc[ct][3] * lihi;
            }
        }
        __syncthreads();
        for (int idx = tid; idx < 128 * 32; idx += 512) {
            int c = idx >> 5, i4 = idx & 31;
            float4 v = *reinterpret_cast<float4*>(smO + c * 132 + i4 * 4);
            *reinterpret_cast<float4*>(
                O + ((size_t)(b * CC + 128 * p + c)) * NN + i0 + i4 * 4) = v;
        }
    }
}

// ---------------- combine: out = x + gamma*(attn + d1 + d3) ----------------------
__global__ void combine_kernel(const float* __restrict__ x, const float* __restrict__ o,
                               const float* __restrict__ d1, const float* __restrict__ d3,
                               const float* __restrict__ gamma, float* __restrict__ out,
                               int total4)
{
    int i = blockIdx.x * blockDim.x + threadIdx.x;
    float g = gamma[0];
    if (i < total4) {
        float4 xv = ((const float4*)x)[i];
        float4 ov = ((const float4*)o)[i];
        float4 dv = ((const float4*)d1)[i];
        float4 ev = ((const float4*)d3)[i];
        float4 r;
        r.x = xv.x + g * (ov.x + dv.x + ev.x);
        r.y = xv.y + g * (ov.y + dv.y + ev.y);
        r.z = xv.z + g * (ov.z + dv.z + ev.z);
        r.w = xv.w + g * (ov.w + dv.w + ev.w);
        ((float4*)out)[i] = r;
    }
}

// ---------------- host launcher --------------------------------------------------
extern "C" void kernel_launch(void* const* d_in, const int* in_sizes, int n_in,
                              void* d_out, int out_size)
{
    (void)in_sizes; (void)n_in; (void)out_size;

    const float* x1  = (const float*)d_in[0];
    const float* x2  = (const float*)d_in[1];
    const float* wq1 = (const float*)d_in[2];
    const float* bq1 = (const float*)d_in[3];
    const float* wk1 = (const float*)d_in[4];
    const float* bk1 = (const float*)d_in[5];
    const float* wv1 = (const float*)d_in[6];
    const float* bv1 = (const float*)d_in[7];
    const float* wq2 = (const float*)d_in[8];
    const float* bq2 = (const float*)d_in[9];
    const float* wk2 = (const float*)d_in[10];
    const float* bk2 = (const float*)d_in[11];
    const float* wv2 = (const float*)d_in[12];
    const float* bv2 = (const float*)d_in[13];
    const float* wd1 = (const float*)d_in[14];
    const float* bd1 = (const float*)d_in[15];
    const float* wd3 = (const float*)d_in[16];
    const float* bd3 = (const float*)d_in[17];
    const float* gm1 = (const float*)d_in[18];
    const float* gm2 = (const float*)d_in[19];
    float* out = (float*)d_out;

    float *p_q1, *p_k1, *p_q2, *p_k2, *p_v1, *p_v2;
    float *p_d1a, *p_d1b, *p_d3a, *p_d3b, *p_o1, *p_o2;
    cudaGetSymbolAddress((void**)&p_q1, g_q1);
    cudaGetSymbolAddress((void**)&p_k1, g_k1);
    cudaGetSymbolAddress((void**)&p_q2, g_q2);
    cudaGetSymbolAddress((void**)&p_k2, g_k2);
    cudaGetSymbolAddress((void**)&p_v1, g_v1);
    cudaGetSymbolAddress((void**)&p_v2, g_v2);
    cudaGetSymbolAddress((void**)&p_d1a, g_d1a);
    cudaGetSymbolAddress((void**)&p_d1b, g_d1b);
    cudaGetSymbolAddress((void**)&p_d3a, g_d3a);
    cudaGetSymbolAddress((void**)&p_d3b, g_d3b);
    cudaGetSymbolAddress((void**)&p_o1, g_o1);
    cudaGetSymbolAddress((void**)&p_o2, g_o2);

    // 1x1 projections
    {
        dim3 blk(256);
        dim3 gQK(NN / 64, 1, BB);
        gemm1x1_kernel<<<gQK, blk>>>(wq1, bq1, x1, p_q1, CKD);
        gemm1x1_kernel<<<gQK, blk>>>(wk1, bk1, x1, p_k1, CKD);
        gemm1x1_kernel<<<gQK, blk>>>(wq2, bq2, x2, p_q2, CKD);
        gemm1x1_kernel<<<gQK, blk>>>(wk2, bk2, x2, p_k2, CKD);
        dim3 gV(NN / 64, CC / 64, BB);
        gemm1x1_kernel<<<gV, blk>>>(wv1, bv1, x1, p_v1, CC);
        gemm1x1_kernel<<<gV, blk>>>(wv2, bv2, x2, p_v2, CC);
        gemm1x1_kernel<<<gV, blk>>>(wd1, bd1, x1, p_d1a, CC);
        gemm1x1_kernel<<<gV, blk>>>(wd1, bd1, x2, p_d1b, CC);
    }

    // 3x3 convs
    {
        dim3 blk(256);
        dim3 g(CC / 64, HH, BB);
        conv3x3_kernel<<<g, blk>>>(wd3, bd3, x1, p_d3a);
        conv3x3_kernel<<<g, blk>>>(wd3, bd3, x2, p_d3b);
    }

    // flash attention (tf32 mma, register-resident S/P)
    {
        cudaFuncSetAttribute(flashattn_mma,
                             cudaFuncAttributeMaxDynamicSharedMemorySize, FA3_SMEM_BYTES);
        dim3 blk(512);
        dim3 g(NN / 128, BB);
        flashattn_mma<<<g, blk, FA3_SMEM_BYTES>>>(p_q1, p_k2, p_v2, p_o1);
        flashattn_mma<<<g, blk, FA3_SMEM_BYTES>>>(p_q2, p_k1, p_v1, p_o2);
    }

    // combine + residual
    {
        int total  = BB * CC * NN;
        int total4 = total / 4;
        int threads = 256;
        int blocks = (total4 + threads - 1) / threads;
        combine_kernel<<<blocks, threads>>>(x1, p_o1, p_d1a, p_d3a, gm1, out, total4);
        combine_kernel<<<blocks, threads>>>(x2, p_o2, p_d1b, p_d3b, gm2, out + total, total4);
    }
}

// round 4
// speedup vs baseline: 2.2511x; 1.2510x over previous
#include <cuda_runtime.h>
#include <cstdint>
#include <cstddef>

#define BB 4
#define CC 256
#define CKD 32
#define NN 4096
#define HH 64
#define WW 64

// ---------------- scratch (device globals; no allocation allowed) ----------------
__device__ float g_q1[BB*CKD*NN];
__device__ float g_k1[BB*CKD*NN];
__device__ float g_q2[BB*CKD*NN];
__device__ float g_k2[BB*CKD*NN];
__device__ float g_v1[BB*CC*NN];
__device__ float g_v2[BB*CC*NN];
__device__ float g_d1a[BB*CC*NN];
__device__ float g_d1b[BB*CC*NN];
__device__ float g_d3a[BB*CC*NN];
__device__ float g_d3b[BB*CC*NN];
__device__ float g_o1[BB*CC*NN];
__device__ float g_o2[BB*CC*NN];

// ---------------- mma helper (raw fp32 bits as tf32: HW truncates) ---------------
__device__ __forceinline__ void mma8(float* c,
                                     uint32_t a0, uint32_t a1, uint32_t a2, uint32_t a3,
                                     uint32_t b0, uint32_t b1) {
    asm volatile(
        "mma.sync.aligned.m16n8k8.row.col.f32.tf32.tf32.f32 "
        "{%0,%1,%2,%3}, {%4,%5,%6,%7}, {%8,%9}, {%0,%1,%2,%3};"
        : "+f"(c[0]), "+f"(c[1]), "+f"(c[2]), "+f"(c[3])
        : "r"(a0), "r"(a1), "r"(a2), "r"(a3), "r"(b0), "r"(b1));
}

__device__ __forceinline__ void cpa16(uint32_t dst, const void* src) {
    asm volatile("cp.async.ca.shared.global [%0], [%1], 16;\n" :: "r"(dst), "l"(src));
}

// ---------------- 1x1 conv as GEMM: Y[b,o,n] = sum_c W[o,c]*X[b,c,n] + bias[o] ----
__global__ void gemm1x1_kernel(const float* __restrict__ W, const float* __restrict__ bias,
                               const float* __restrict__ X, float* __restrict__ Y, int O)
{
    const int n0 = blockIdx.x * 64;
    const int o0 = blockIdx.y * 64;
    const int b  = blockIdx.z;

    __shared__ float Ws[16][64];
    __shared__ float Xs[16][64];

    const int tx = threadIdx.x & 15;
    const int ty = threadIdx.x >> 4;

    float acc[4][4];
#pragma unroll
    for (int m = 0; m < 4; m++)
#pragma unroll
        for (int n = 0; n < 4; n++) acc[m][n] = 0.f;

    const float* Xb = X + (size_t)b * CC * NN;

    for (int k0 = 0; k0 < CC; k0 += 16) {
#pragma unroll
        for (int i = 0; i < 4; i++) {
            int idx = threadIdx.x + i * 256;
            int e  = idx & 63;
            int kc = idx >> 6;
            float wv = 0.f;
            if (o0 + e < O) wv = W[(size_t)(o0 + e) * CC + k0 + kc];
            Ws[kc][e] = wv;
            Xs[kc][e] = Xb[(size_t)(k0 + kc) * NN + n0 + e];
        }
        __syncthreads();
#pragma unroll
        for (int kc = 0; kc < 16; kc++) {
            float a[4], bv[4];
#pragma unroll
            for (int m = 0; m < 4; m++) a[m] = Ws[kc][ty * 4 + m];
#pragma unroll
            for (int n = 0; n < 4; n++) bv[n] = Xs[kc][tx * 4 + n];
#pragma unroll
            for (int m = 0; m < 4; m++)
#pragma unroll
                for (int n = 0; n < 4; n++) acc[m][n] += a[m] * bv[n];
        }
        __syncthreads();
    }

#pragma unroll
    for (int m = 0; m < 4; m++) {
        int o = o0 + ty * 4 + m;
        if (o < O) {
            float bo = bias[o];
#pragma unroll
            for (int n = 0; n < 4; n++)
                Y[((size_t)b * O + o) * NN + n0 + tx * 4 + n] = acc[m][n] + bo;
        }
    }
}

// ---------------- direct 3x3 conv (SAME, zero pad) -------------------------------
__global__ void conv3x3_kernel(const float* __restrict__ W3, const float* __restrict__ bias,
                               const float* __restrict__ X, float* __restrict__ Y)
{
    const int o0 = blockIdx.x * 64;
    const int h  = blockIdx.y;
    const int b  = blockIdx.z;

    __shared__ float Ws[8][9][64];
    __shared__ float Xs[8][3][72];

    const int tx = threadIdx.x & 15;
    const int ty = threadIdx.x >> 4;

    float acc[4][4];
#pragma unroll
    for (int m = 0; m < 4; m++)
#pragma unroll
        for (int n = 0; n < 4; n++) acc[m][n] = 0.f;

    const float* Xb = X + (size_t)b * CC * NN;

    for (int c0 = 0; c0 < CC; c0 += 8) {
        for (int idx = threadIdx.x; idx < 8 * 3 * 72; idx += 256) {
            int kc = idx / (3 * 72);
            int r  = (idx / 72) % 3;
            int wc = idx % 72;
            float v = 0.f;
            int hh = h + r - 1;
            int ww = wc - 1;
            if (hh >= 0 && hh < HH && ww >= 0 && ww < WW)
                v = Xb[(size_t)(c0 + kc) * NN + hh * WW + ww];
            Xs[kc][r][wc] = v;
        }
        for (int idx = threadIdx.x; idx < 8 * 9 * 64; idx += 256) {
            int o  = idx & 63;
            int k9 = (idx >> 6) % 9;
            int kc = idx / (64 * 9);
            Ws[kc][k9][o] = W3[((size_t)(o0 + o) * CC + c0 + kc) * 9 + k9];
        }
        __syncthreads();
#pragma unroll
        for (int kc = 0; kc < 8; kc++) {
#pragma unroll
            for (int r = 0; r < 3; r++) {
                float xv[6];
#pragma unroll
                for (int n = 0; n < 6; n++) xv[n] = Xs[kc][r][tx * 4 + n];
#pragma unroll
                for (int kx = 0; kx < 3; kx++) {
                    float wv[4];
#pragma unroll
                    for (int m = 0; m < 4; m++) wv[m] = Ws[kc][r * 3 + kx][ty * 4 + m];
#pragma unroll
                    for (int m = 0; m < 4; m++)
#pragma unroll
                        for (int n = 0; n < 4; n++)
                            acc[m][n] += wv[m] * xv[n + kx];
                }
            }
        }
        __syncthreads();
    }

#pragma unroll
    for (int m = 0; m < 4; m++) {
        int o = o0 + ty * 4 + m;
        float bo = bias[o];
#pragma unroll
        for (int n = 0; n < 4; n++)
            Y[((size_t)b * CC + o) * NN + h * WW + tx * 4 + n] = acc[m][n] + bo;
    }
}

// ---------------- flash attention v4 ---------------------------------------------
// 256 threads (8 warps = 4 m-groups x 2 c-halves), BM=64, BN=64.
// cp.async double-buffered K[d][j] (stride 72) and V[c][j] (stride 68) tiles.
// S/P fully register-resident; raw fp32 bits fed to mma.tf32.
#define FA4_SMQ 0
#define FA4_QSTRIDE 36
#define FA4_SMK 2304
#define FA4_KSTRIDE 72
#define FA4_KBUF 2304                    // 32*72
#define FA4_SMV (FA4_SMK + 2 * FA4_KBUF) // 6912
#define FA4_VSTRIDE 68
#define FA4_VBUF 17408                   // 256*68
#define FA4_SMEM_FLOATS (FA4_SMV + 2 * FA4_VBUF)   // 41728
#define FA4_SMEM_BYTES (FA4_SMEM_FLOATS * 4)       // 166912

__global__ __launch_bounds__(256, 1)
void flashattn_mma(const float* __restrict__ Q, const float* __restrict__ K,
                   const float* __restrict__ V, float* __restrict__ O)
{
    extern __shared__ float sm[];
    float* Qs = sm + FA4_SMQ;

    const int tid  = threadIdx.x;
    const int w    = tid >> 5;
    const int lane = tid & 31;
    const int g    = lane >> 2;
    const int qb   = lane & 3;
    const int wm   = w & 3;     // m-group (16 rows of 64)
    const int cw   = w >> 2;    // c half
    const int i0   = blockIdx.x * 64;
    const int b    = blockIdx.y;
    const bool odd = qb & 1;
    const int srcA = (lane & ~3) | (qb >> 1);
    const int srcB = srcA + 2;

    const float* Qb = Q + (size_t)b * CKD * NN;
    const float* Kb = K + (size_t)b * CKD * NN;
    const float* Vb = V + (size_t)b * CC * NN;

    const uint32_t smb = (uint32_t)__cvta_generic_to_shared(sm);

    // ---- prologue: issue cp.async for tile 0 (buffer 0) ----
    {
        const int cidK = tid;               // 512 K chunks: 2 per thread
#pragma unroll
        for (int it = 0; it < 2; it++) {
            int cid = cidK + it * 256;
            int d = cid >> 4, jc = (cid & 15) * 4;
            cpa16(smb + (FA4_SMK + d * FA4_KSTRIDE + jc) * 4, Kb + (size_t)d * NN + jc);
        }
#pragma unroll
        for (int it = 0; it < 16; it++) {   // 4096 V chunks: 16 per thread
            int cid = tid + it * 256;
            int c = cid >> 4, jc = (cid & 15) * 4;
            cpa16(smb + (FA4_SMV + c * FA4_VSTRIDE + jc) * 4, Vb + (size_t)c * NN + jc);
        }
        asm volatile("cp.async.commit_group;");
    }

    // ---- load Q tile (64 x 32) transposed -> [i][d] raw bits ----
    for (int idx = tid; idx < 64 * CKD; idx += 256) {
        int i = idx & 63, d = idx >> 6;
        Qs[i * FA4_QSTRIDE + d] = Qb[(size_t)d * NN + i0 + i];
    }
    __syncthreads();

    uint32_t aq[4][4];
#pragma unroll
    for (int kk = 0; kk < 4; kk++) {
        const int d0 = 8 * kk;
        const int br = 16 * wm;
        aq[kk][0] = __float_as_uint(Qs[(br + g) * FA4_QSTRIDE + d0 + qb]);
        aq[kk][1] = __float_as_uint(Qs[(br + g + 8) * FA4_QSTRIDE + d0 + qb]);
        aq[kk][2] = __float_as_uint(Qs[(br + g) * FA4_QSTRIDE + d0 + qb + 4]);
        aq[kk][3] = __float_as_uint(Qs[(br + g + 8) * FA4_QSTRIDE + d0 + qb + 4]);
    }

    float acc[16][4];
#pragma unroll
    for (int ct = 0; ct < 16; ct++)
#pragma unroll
        for (int e = 0; e < 4; e++) acc[ct][e] = 0.f;

    float mlo = -1e30f, mhi = -1e30f, llo = 0.f, lhi = 0.f;

    for (int t = 0; t < NN / 64; t++) {
        const int cur = t & 1;

        asm volatile("cp.async.wait_group 0;");
        __syncthreads();   // tile t resident; all warps done with other buffer

        if (t + 1 < NN / 64) {
            const int j0n = (t + 1) * 64;
            const int nb  = 1 - cur;
#pragma unroll
            for (int it = 0; it < 2; it++) {
                int cid = tid + it * 256;
                int d = cid >> 4, jc = (cid & 15) * 4;
                cpa16(smb + (FA4_SMK + nb * FA4_KBUF + d * FA4_KSTRIDE + jc) * 4,
                      Kb + (size_t)d * NN + j0n + jc);
            }
#pragma unroll
            for (int it = 0; it < 16; it++) {
                int cid = tid + it * 256;
                int c = cid >> 4, jc = (cid & 15) * 4;
                cpa16(smb + (FA4_SMV + nb * FA4_VBUF + c * FA4_VSTRIDE + jc) * 4,
                      Vb + (size_t)c * NN + j0n + jc);
            }
            asm volatile("cp.async.commit_group;");
        }

        const float* Ks = sm + FA4_SMK + cur * FA4_KBUF;   // [d][72]
        const float* Vs = sm + FA4_SMV + cur * FA4_VBUF;   // [c][68]

        // ---- S = Q K^T ----
        float s[8][4];
#pragma unroll
        for (int nt = 0; nt < 8; nt++)
#pragma unroll
            for (int e = 0; e < 4; e++) s[nt][e] = 0.f;

#pragma unroll
        for (int kk = 0; kk < 4; kk++) {
            const int d0 = 8 * kk;
#pragma unroll
            for (int nt = 0; nt < 8; nt++) {
                uint32_t b0 = __float_as_uint(Ks[(d0 + qb) * FA4_KSTRIDE + 8 * nt + g]);
                uint32_t b1 = __float_as_uint(Ks[(d0 + qb + 4) * FA4_KSTRIDE + 8 * nt + g]);
                mma8(s[nt], aq[kk][0], aq[kk][1], aq[kk][2], aq[kk][3], b0, b1);
            }
        }

        // ---- online softmax in registers ----
        {
            float pmlo = -1e30f, pmhi = -1e30f;
#pragma unroll
            for (int nt = 0; nt < 8; nt++) {
                pmlo = fmaxf(pmlo, fmaxf(s[nt][0], s[nt][1]));
                pmhi = fmaxf(pmhi, fmaxf(s[nt][2], s[nt][3]));
            }
            pmlo = fmaxf(pmlo, __shfl_xor_sync(0xffffffffu, pmlo, 1));
            pmlo = fmaxf(pmlo, __shfl_xor_sync(0xffffffffu, pmlo, 2));
            pmhi = fmaxf(pmhi, __shfl_xor_sync(0xffffffffu, pmhi, 1));
            pmhi = fmaxf(pmhi, __shfl_xor_sync(0xffffffffu, pmhi, 2));

            float mlo_n = fmaxf(mlo, pmlo);
            float mhi_n = fmaxf(mhi, pmhi);
            float alo = __expf(mlo - mlo_n);
            float ahi = __expf(mhi - mhi_n);

            float slo = 0.f, shi = 0.f;
#pragma unroll
            for (int nt = 0; nt < 8; nt++) {
                s[nt][0] = __expf(s[nt][0] - mlo_n);
                s[nt][1] = __expf(s[nt][1] - mlo_n);
                s[nt][2] = __expf(s[nt][2] - mhi_n);
                s[nt][3] = __expf(s[nt][3] - mhi_n);
                slo += s[nt][0] + s[nt][1];
                shi += s[nt][2] + s[nt][3];
            }
            slo += __shfl_xor_sync(0xffffffffu, slo, 1);
            slo += __shfl_xor_sync(0xffffffffu, slo, 2);
            shi += __shfl_xor_sync(0xffffffffu, shi, 1);
            shi += __shfl_xor_sync(0xffffffffu, shi, 2);

            llo = llo * alo + slo;
            lhi = lhi * ahi + shi;
            mlo = mlo_n; mhi = mhi_n;

#pragma unroll
            for (int ct = 0; ct < 16; ct++) {
                acc[ct][0] *= alo; acc[ct][1] *= alo;
                acc[ct][2] *= ahi; acc[ct][3] *= ahi;
            }
        }

        // ---- O += P V (C-frag -> A-frag permute via shuffles) ----
#pragma unroll
        for (int kk = 0; kk < 8; kk++) {
            float x0 = __shfl_sync(0xffffffffu, s[kk][0], srcA);
            float x1 = __shfl_sync(0xffffffffu, s[kk][1], srcA);
            float y0 = __shfl_sync(0xffffffffu, s[kk][0], srcB);
            float y1 = __shfl_sync(0xffffffffu, s[kk][1], srcB);
            float z0 = __shfl_sync(0xffffffffu, s[kk][2], srcA);
            float z1 = __shfl_sync(0xffffffffu, s[kk][3], srcA);
            float w0 = __shfl_sync(0xffffffffu, s[kk][2], srcB);
            float w1 = __shfl_sync(0xffffffffu, s[kk][3], srcB);
            uint32_t a0 = __float_as_uint(odd ? x1 : x0);
            uint32_t a1 = __float_as_uint(odd ? z1 : z0);
            uint32_t a2 = __float_as_uint(odd ? y1 : y0);
            uint32_t a3 = __float_as_uint(odd ? w1 : w0);

            const int jk = 8 * kk;
#pragma unroll
            for (int ct = 0; ct < 16; ct++) {
                const int c0 = 128 * cw + 8 * ct;
                uint32_t b0 = __float_as_uint(Vs[(c0 + g) * FA4_VSTRIDE + jk + qb]);
                uint32_t b1 = __float_as_uint(Vs[(c0 + g) * FA4_VSTRIDE + jk + qb + 4]);
                mma8(acc[ct], a0, a1, a2, a3, b0, b1);
            }
        }
    }
    __syncthreads();

    // ---- epilogue: normalize, stage via smem (reuse V buffers), store ----
    const float lilo = 1.f / llo;
    const float lihi = 1.f / lhi;
    float* smO = sm + FA4_SMV;   // [128 c][68]

    for (int p = 0; p < 2; p++) {
        __syncthreads();
        if (cw == p) {
#pragma unroll
            for (int ct = 0; ct < 16; ct++) {
                const int rr = 16 * wm + g;
                const int cl = 8 * ct + 2 * qb;
                smO[cl * FA4_VSTRIDE + rr]           = acc[ct][0] * lilo;
                smO[(cl + 1) * FA4_VSTRIDE + rr]     = acc[ct][1] * lilo;
                smO[cl * FA4_VSTRIDE + rr + 8]       = acc[ct][2] * lihi;
                smO[(cl + 1) * FA4_VSTRIDE + rr + 8] = acc[ct][3] * lihi;
            }
        }
        __syncthreads();
        for (int idx = tid; idx < 128 * 16; idx += 256) {
            int c = idx >> 4, i4 = idx & 15;
            float4 v = *reinterpret_cast<float4*>(smO + c * FA4_VSTRIDE + i4 * 4);
            *reinterpret_cast<float4*>(
                O + ((size_t)(b * CC + 128 * p + c)) * NN + i0 + i4 * 4) = v;
        }
    }
}

// ---------------- combine: out = x + gamma*(attn + d1 + d3) ----------------------
__global__ void combine_kernel(const float* __restrict__ x, const float* __restrict__ o,
                               const float* __restrict__ d1, const float* __restrict__ d3,
                               const float* __restrict__ gamma, float* __restrict__ out,
                               int total4)
{
    int i = blockIdx.x * blockDim.x + threadIdx.x;
    float g = gamma[0];
    if (i < total4) {
        float4 xv = ((const float4*)x)[i];
        float4 ov = ((const float4*)o)[i];
        float4 dv = ((const float4*)d1)[i];
        float4 ev = ((const float4*)d3)[i];
        float4 r;
        r.x = xv.x + g * (ov.x + dv.x + ev.x);
        r.y = xv.y + g * (ov.y + dv.y + ev.y);
        r.z = xv.z + g * (ov.z + dv.z + ev.z);
        r.w = xv.w + g * (ov.w + dv.w + ev.w);
        ((float4*)out)[i] = r;
    }
}

// ---------------- host launcher --------------------------------------------------
extern "C" void kernel_launch(void* const* d_in, const int* in_sizes, int n_in,
                              void* d_out, int out_size)
{
    (void)in_sizes; (void)n_in; (void)out_size;

    const float* x1  = (const float*)d_in[0];
    const float* x2  = (const float*)d_in[1];
    const float* wq1 = (const float*)d_in[2];
    const float* bq1 = (const float*)d_in[3];
    const float* wk1 = (const float*)d_in[4];
    const float* bk1 = (const float*)d_in[5];
    const float* wv1 = (const float*)d_in[6];
    const float* bv1 = (const float*)d_in[7];
    const float* wq2 = (const float*)d_in[8];
    const float* bq2 = (const float*)d_in[9];
    const float* wk2 = (const float*)d_in[10];
    const float* bk2 = (const float*)d_in[11];
    const float* wv2 = (const float*)d_in[12];
    const float* bv2 = (const float*)d_in[13];
    const float* wd1 = (const float*)d_in[14];
    const float* bd1 = (const float*)d_in[15];
    const float* wd3 = (const float*)d_in[16];
    const float* bd3 = (const float*)d_in[17];
    const float* gm1 = (const float*)d_in[18];
    const float* gm2 = (const float*)d_in[19];
    float* out = (float*)d_out;

    float *p_q1, *p_k1, *p_q2, *p_k2, *p_v1, *p_v2;
    float *p_d1a, *p_d1b, *p_d3a, *p_d3b, *p_o1, *p_o2;
    cudaGetSymbolAddress((void**)&p_q1, g_q1);
    cudaGetSymbolAddress((void**)&p_k1, g_k1);
    cudaGetSymbolAddress((void**)&p_q2, g_q2);
    cudaGetSymbolAddress((void**)&p_k2, g_k2);
    cudaGetSymbolAddress((void**)&p_v1, g_v1);
    cudaGetSymbolAddress((void**)&p_v2, g_v2);
    cudaGetSymbolAddress((void**)&p_d1a, g_d1a);
    cudaGetSymbolAddress((void**)&p_d1b, g_d1b);
    cudaGetSymbolAddress((void**)&p_d3a, g_d3a);
    cudaGetSymbolAddress((void**)&p_d3b, g_d3b);
    cudaGetSymbolAddress((void**)&p_o1, g_o1);
    cudaGetSymbolAddress((void**)&p_o2, g_o2);

    // 1x1 projections
    {
        dim3 blk(256);
        dim3 gQK(NN / 64, 1, BB);
        gemm1x1_kernel<<<gQK, blk>>>(wq1, bq1, x1, p_q1, CKD);
        gemm1x1_kernel<<<gQK, blk>>>(wk1, bk1, x1, p_k1, CKD);
        gemm1x1_kernel<<<gQK, blk>>>(wq2, bq2, x2, p_q2, CKD);
        gemm1x1_kernel<<<gQK, blk>>>(wk2, bk2, x2, p_k2, CKD);
        dim3 gV(NN / 64, CC / 64, BB);
        gemm1x1_kernel<<<gV, blk>>>(wv1, bv1, x1, p_v1, CC);
        gemm1x1_kernel<<<gV, blk>>>(wv2, bv2, x2, p_v2, CC);
        gemm1x1_kernel<<<gV, blk>>>(wd1, bd1, x1, p_d1a, CC);
        gemm1x1_kernel<<<gV, blk>>>(wd1, bd1, x2, p_d1b, CC);
    }

    // 3x3 convs
    {
        dim3 blk(256);
        dim3 g(CC / 64, HH, BB);
        conv3x3_kernel<<<g, blk>>>(wd3, bd3, x1, p_d3a);
        conv3x3_kernel<<<g, blk>>>(wd3, bd3, x2, p_d3b);
    }

    // flash attention (tf32 mma, cp.async double buffer, no spills)
    {
        cudaFuncSetAttribute(flashattn_mma,
                             cudaFuncAttributeMaxDynamicSharedMemorySize, FA4_SMEM_BYTES);
        dim3 blk(256);
        dim3 g(NN / 64, BB);
        flashattn_mma<<<g, blk, FA4_SMEM_BYTES>>>(p_q1, p_k2, p_v2, p_o1);
        flashattn_mma<<<g, blk, FA4_SMEM_BYTES>>>(p_q2, p_k1, p_v1, p_o2);
    }

    // combine + residual
    {
        int total  = BB * CC * NN;
        int total4 = total / 4;
        int threads = 256;
        int blocks = (total4 + threads - 1) / threads;
        combine_kernel<<<blocks, threads>>>(x1, p_o1, p_d1a, p_d3a, gm1, out, total4);
        combine_kernel<<<blocks, threads>>>(x2, p_o2, p_d1b, p_d3b, gm2, out + total, total4);
    }
}

// round 5
// speedup vs baseline: 6.6692x; 2.9627x over previous
#include <cuda_runtime.h>
#include <cstdint>
#include <cstddef>

#define BB 4
#define CC 256
#define CKD 32
#define NN 4096
#define HH 64
#define WW 64
#define OP 576   // packed projection rows: 256 v + 256 d1 + 32 q + 32 k

// ---------------- scratch (device globals; no allocation allowed) ----------------
__device__ float g_Wp[2][OP][CC];       // packed weights per side
__device__ float g_bp[2][OP];           // packed bias per side
__device__ float g_pk[2][BB][OP][NN];   // packed projection outputs
__device__ float g_d3[2][BB][CC][NN];   // conv3x3 outputs
__device__ float g_o1[BB*CC*NN];
__device__ float g_o2[BB*CC*NN];

// ---------------- helpers --------------------------------------------------------
__device__ __forceinline__ void mma8(float* c,
                                     uint32_t a0, uint32_t a1, uint32_t a2, uint32_t a3,
                                     uint32_t b0, uint32_t b1) {
    asm volatile(
        "mma.sync.aligned.m16n8k8.row.col.f32.tf32.tf32.f32 "
        "{%0,%1,%2,%3}, {%4,%5,%6,%7}, {%8,%9}, {%0,%1,%2,%3};"
        : "+f"(c[0]), "+f"(c[1]), "+f"(c[2]), "+f"(c[3])
        : "r"(a0), "r"(a1), "r"(a2), "r"(a3), "r"(b0), "r"(b1));
}
__device__ __forceinline__ void cpa16(uint32_t dst, const void* src) {
    asm volatile("cp.async.ca.shared.global [%0], [%1], 16;\n" :: "r"(dst), "l"(src));
}
__device__ __forceinline__ void cpa4(uint32_t dst, const void* src) {
    asm volatile("cp.async.ca.shared.global [%0], [%1], 4;\n" :: "r"(dst), "l"(src));
}
__device__ __forceinline__ void cp_commit() { asm volatile("cp.async.commit_group;"); }
__device__ __forceinline__ void cp_wait0()  { asm volatile("cp.async.wait_group 0;"); }

// ---------------- weight packing -------------------------------------------------
// rows 0-255: wv, 256-511: wd1, 512-543: wq, 544-575: wk
__global__ void pack_weights(const float* __restrict__ wv1, const float* __restrict__ bv1,
                             const float* __restrict__ wd1, const float* __restrict__ bd1,
                             const float* __restrict__ wq1, const float* __restrict__ bq1,
                             const float* __restrict__ wk1, const float* __restrict__ bk1,
                             const float* __restrict__ wv2, const float* __restrict__ bv2,
                             const float* __restrict__ wq2, const float* __restrict__ bq2,
                             const float* __restrict__ wk2, const float* __restrict__ bk2)
{
    int row = blockIdx.x;
    int side = blockIdx.y;
    const float *w, *bs; int r;
    if (row < 256)      { w = side ? wv2 : wv1; bs = side ? bv2 : bv1; r = row; }
    else if (row < 512) { w = wd1;              bs = bd1;              r = row - 256; }
    else if (row < 544) { w = side ? wq2 : wq1; bs = side ? bq2 : bq1; r = row - 512; }
    else                { w = side ? wk2 : wk1; bs = side ? bk2 : bk1; r = row - 544; }
    g_Wp[side][row][threadIdx.x] = w[r * CC + threadIdx.x];
    if (threadIdx.x == 0) g_bp[side][row] = bs[r];
}

// ---------------- fused 1x1 projections via tf32 mma -----------------------------
// grid (NN/128, OP/64, 8): z = side*4 + b. 256 threads, 8 warps = 4 m x 2 n-halves.
__global__ __launch_bounds__(256) void proj_mma(const float* __restrict__ X1,
                                                const float* __restrict__ X2)
{
    __shared__ float Ws[2][64][36];
    __shared__ float Xs[2][16][136];

    const int tid = threadIdx.x;
    const int w = tid >> 5, lane = tid & 31, g = lane >> 2, qb = lane & 3;
    const int mo = w & 3, nh = w >> 2;
    const int n0 = blockIdx.x * 128, o0 = blockIdx.y * 64;
    const int z = blockIdx.z, side = z >> 2, b = z & 3;
    const float* X = (side ? X2 : X1) + (size_t)b * CC * NN;
    const float* Wp = &g_Wp[side][0][0];
    float* Y = &g_pk[side][b][0][0];

    const uint32_t sw = (uint32_t)__cvta_generic_to_shared(&Ws[0][0][0]);
    const uint32_t sx = (uint32_t)__cvta_generic_to_shared(&Xs[0][0][0]);

    const int wo = tid >> 2, wc4 = (tid & 3) * 4;   // W job
    // issue chunk c0 into buf
    auto issue = [&](int buf, int c0) {
        cpa16(sw + (uint32_t)(buf * 2304 + wo * 36 + wc4) * 4,
              Wp + (size_t)(o0 + wo) * CC + c0 + wc4);
#pragma unroll
        for (int it = 0; it < 2; it++) {
            int cid = tid + it * 256;
            int c = cid >> 5, nc = (cid & 31) * 4;
            cpa16(sx + (uint32_t)(buf * 2176 + c * 136 + nc) * 4,
                  X + (size_t)(c0 + c) * NN + n0 + nc);
        }
        cp_commit();
    };

    float acc[8][4];
#pragma unroll
    for (int nt = 0; nt < 8; nt++)
#pragma unroll
        for (int e = 0; e < 4; e++) acc[nt][e] = 0.f;

    issue(0, 0);
    for (int kc = 0; kc < 16; kc++) {
        const int cur = kc & 1;
        cp_wait0();
        __syncthreads();
        if (kc < 15) issue(cur ^ 1, 16 * (kc + 1));
#pragma unroll
        for (int ks = 0; ks < 2; ks++) {
            const int k0 = 8 * ks;
            uint32_t a0 = __float_as_uint(Ws[cur][16 * mo + g][k0 + qb]);
            uint32_t a1 = __float_as_uint(Ws[cur][16 * mo + g + 8][k0 + qb]);
            uint32_t a2 = __float_as_uint(Ws[cur][16 * mo + g][k0 + qb + 4]);
            uint32_t a3 = __float_as_uint(Ws[cur][16 * mo + g + 8][k0 + qb + 4]);
#pragma unroll
            for (int nt = 0; nt < 8; nt++) {
                uint32_t b0 = __float_as_uint(Xs[cur][k0 + qb][64 * nh + 8 * nt + g]);
                uint32_t b1 = __float_as_uint(Xs[cur][k0 + qb + 4][64 * nh + 8 * nt + g]);
                mma8(acc[nt], a0, a1, a2, a3, b0, b1);
            }
        }
        __syncthreads();
    }

    const int olo = o0 + 16 * mo + g, ohi = olo + 8;
    const float blo = g_bp[side][olo], bhi = g_bp[side][ohi];
#pragma unroll
    for (int nt = 0; nt < 8; nt++) {
        int n = n0 + 64 * nh + 8 * nt + 2 * qb;
        float2 v0; v0.x = acc[nt][0] + blo; v0.y = acc[nt][1] + blo;
        *(float2*)(Y + (size_t)olo * NN + n) = v0;
        float2 v1; v1.x = acc[nt][2] + bhi; v1.y = acc[nt][3] + bhi;
        *(float2*)(Y + (size_t)ohi * NN + n) = v1;
    }
}

// ---------------- 3x3 conv via tf32 mma (implicit GEMM) --------------------------
// grid (CC/64, HH/4, 8): z = side*4 + b. Block: 64 o x 4 h-rows x 64 w.
// 256 threads, 8 warps = 4 m-groups x 2 row-pairs.
#define CV_SO 100
#define CV_XR 68
#define CV_XC 408                                // 6*68
#define CV_WS 6400                               // 64*100
#define CV_XS 3264                               // 8*408
#define CV_SMEM_BYTES ((2 * (CV_WS + CV_XS)) * 4)   // 77312

__global__ __launch_bounds__(256) void conv3x3_mma(
    const float* __restrict__ X1, const float* __restrict__ X2,
    const float* __restrict__ W3, const float* __restrict__ bias)
{
    extern __shared__ float csm[];
    float* Ws = csm;                    // [2][64][100]
    float* Xs = csm + 2 * CV_WS;        // [2][8][6][68]

    const int tid = threadIdx.x;
    const int w = tid >> 5, lane = tid & 31, g = lane >> 2, qb = lane & 3;
    const int mo = w & 3, sh = w >> 2;
    const int o0 = blockIdx.x * 64;
    const int hg = blockIdx.y;
    const int z = blockIdx.z, side = z >> 2, b = z & 3;
    const float* X = (side ? X2 : X1) + (size_t)b * CC * NN;
    float* Y = &g_d3[side][b][0][0];

    const uint32_t sw = (uint32_t)__cvta_generic_to_shared(Ws);
    const uint32_t sx = (uint32_t)__cvta_generic_to_shared(Xs);

    // zero X buffers (halo cols / invalid rows stay zero forever)
    for (int i = tid; i < 2 * CV_XS; i += 256) Xs[i] = 0.f;
    __syncthreads();

    auto issue = [&](int buf, int c0) {
#pragma unroll
        for (int it = 0; it < 5; it++) {        // W: 1152 16B-chunks
            int idx = tid + it * 256;
            if (idx < 1152) {
                int o = idx / 18, ch = (idx % 18) * 4;
                cpa16(sw + (uint32_t)(buf * CV_WS + o * CV_SO + ch) * 4,
                      W3 + ((size_t)(o0 + o) * CC + c0) * 9 + ch);
            }
        }
#pragma unroll
        for (int it = 0; it < 12; it++) {       // X: 3072 4B-words
            int idx = tid + it * 256;
            int c = idx / 384, rem = idx - c * 384;
            int r = rem >> 6, wv = rem & 63;
            int h_in = 4 * hg + r - 1;
            if (h_in >= 0 && h_in < HH)
                cpa4(sx + (uint32_t)(buf * CV_XS + c * CV_XC + r * CV_XR + 1 + wv) * 4,
                     X + (size_t)(c0 + c) * NN + h_in * WW + wv);
        }
        cp_commit();
    };

    float acc[16][4];
#pragma unroll
    for (int nt = 0; nt < 16; nt++)
#pragma unroll
        for (int e = 0; e < 4; e++) acc[nt][e] = 0.f;

    issue(0, 0);
    for (int cc = 0; cc < 32; cc++) {
        const int cur = cc & 1;
        cp_wait0();
        __syncthreads();
        if (cc < 31) issue(cur ^ 1, 8 * (cc + 1));
        const float* Wc = Ws + cur * CV_WS;
        const float* Xc = Xs + cur * CV_XS;
#pragma unroll
        for (int ky = 0; ky < 3; ky++) {
#pragma unroll
            for (int kx = 0; kx < 3; kx++) {
                const int tap = ky * 3 + kx;
                uint32_t a0 = __float_as_uint(Wc[(16 * mo + g) * CV_SO + qb * 9 + tap]);
                uint32_t a1 = __float_as_uint(Wc[(16 * mo + g + 8) * CV_SO + qb * 9 + tap]);
                uint32_t a2 = __float_as_uint(Wc[(16 * mo + g) * CV_SO + (qb + 4) * 9 + tap]);
                uint32_t a3 = __float_as_uint(Wc[(16 * mo + g + 8) * CV_SO + (qb + 4) * 9 + tap]);
#pragma unroll
                for (int nt = 0; nt < 16; nt++) {
                    int r = 2 * sh + (nt >> 3) + ky;
                    int col = (nt & 7) * 8 + g + kx;
                    uint32_t b0 = __float_as_uint(Xc[qb * CV_XC + r * CV_XR + col]);
                    uint32_t b1 = __float_as_uint(Xc[(qb + 4) * CV_XC + r * CV_XR + col]);
                    mma8(acc[nt], a0, a1, a2, a3, b0, b1);
                }
            }
        }
        __syncthreads();
    }

    const float blo = bias[o0 + 16 * mo + g], bhi = bias[o0 + 16 * mo + g + 8];
#pragma unroll
    for (int nt = 0; nt < 16; nt++) {
        int h = 4 * hg + 2 * sh + (nt >> 3);
        int wv = (nt & 7) * 8 + 2 * qb;
        size_t base = (size_t)(o0 + 16 * mo + g) * NN + h * WW + wv;
        float2 v0; v0.x = acc[nt][0] + blo; v0.y = acc[nt][1] + blo;
        *(float2*)(Y + base) = v0;
        float2 v1; v1.x = acc[nt][2] + bhi; v1.y = acc[nt][3] + bhi;
        *(float2*)(Y + base + (size_t)8 * NN) = v1;
    }
}

// ---------------- flash attention v4 (unchanged core, batch-stride params) -------
#define FA4_SMQ 0
#define FA4_QSTRIDE 36
#define FA4_SMK 2304
#define FA4_KSTRIDE 72
#define FA4_KBUF 2304
#define FA4_SMV (FA4_SMK + 2 * FA4_KBUF)
#define FA4_VSTRIDE 68
#define FA4_VBUF 17408
#define FA4_SMEM_FLOATS (FA4_SMV + 2 * FA4_VBUF)
#define FA4_SMEM_BYTES (FA4_SMEM_FLOATS * 4)

__global__ __launch_bounds__(256, 1)
void flashattn_mma(const float* __restrict__ Q, const float* __restrict__ K,
                   const float* __restrict__ V, float* __restrict__ O, size_t bstr)
{
    extern __shared__ float sm[];
    float* Qs = sm + FA4_SMQ;

    const int tid  = threadIdx.x;
    const int w    = tid >> 5;
    const int lane = tid & 31;
    const int g    = lane >> 2;
    const int qb   = lane & 3;
    const int wm   = w & 3;
    const int cw   = w >> 2;
    const int i0   = blockIdx.x * 64;
    const int b    = blockIdx.y;
    const bool odd = qb & 1;
    const int srcA = (lane & ~3) | (qb >> 1);
    const int srcB = srcA + 2;

    const float* Qb = Q + (size_t)b * bstr;
    const float* Kb = K + (size_t)b * bstr;
    const float* Vb = V + (size_t)b * bstr;

    const uint32_t smb = (uint32_t)__cvta_generic_to_shared(sm);

    {
#pragma unroll
        for (int it = 0; it < 2; it++) {
            int cid = tid + it * 256;
            int d = cid >> 4, jc = (cid & 15) * 4;
            cpa16(smb + (FA4_SMK + d * FA4_KSTRIDE + jc) * 4, Kb + (size_t)d * NN + jc);
        }
#pragma unroll
        for (int it = 0; it < 16; it++) {
            int cid = tid + it * 256;
            int c = cid >> 4, jc = (cid & 15) * 4;
            cpa16(smb + (FA4_SMV + c * FA4_VSTRIDE + jc) * 4, Vb + (size_t)c * NN + jc);
        }
        cp_commit();
    }

    for (int idx = tid; idx < 64 * CKD; idx += 256) {
        int i = idx & 63, d = idx >> 6;
        Qs[i * FA4_QSTRIDE + d] = Qb[(size_t)d * NN + i0 + i];
    }
    __syncthreads();

    uint32_t aq[4][4];
#pragma unroll
    for (int kk = 0; kk < 4; kk++) {
        const int d0 = 8 * kk;
        const int br = 16 * wm;
        aq[kk][0] = __float_as_uint(Qs[(br + g) * FA4_QSTRIDE + d0 + qb]);
        aq[kk][1] = __float_as_uint(Qs[(br + g + 8) * FA4_QSTRIDE + d0 + qb]);
        aq[kk][2] = __float_as_uint(Qs[(br + g) * FA4_QSTRIDE + d0 + qb + 4]);
        aq[kk][3] = __float_as_uint(Qs[(br + g + 8) * FA4_QSTRIDE + d0 + qb + 4]);
    }

    float acc[16][4];
#pragma unroll
    for (int ct = 0; ct < 16; ct++)
#pragma unroll
        for (int e = 0; e < 4; e++) acc[ct][e] = 0.f;

    float mlo = -1e30f, mhi = -1e30f, llo = 0.f, lhi = 0.f;

    for (int t = 0; t < NN / 64; t++) {
        const int cur = t & 1;
        cp_wait0();
        __syncthreads();

        if (t + 1 < NN / 64) {
            const int j0n = (t + 1) * 64;
            const int nb  = 1 - cur;
#pragma unroll
            for (int it = 0; it < 2; it++) {
                int cid = tid + it * 256;
                int d = cid >> 4, jc = (cid & 15) * 4;
                cpa16(smb + (FA4_SMK + nb * FA4_KBUF + d * FA4_KSTRIDE + jc) * 4,
                      Kb + (size_t)d * NN + j0n + jc);
            }
#pragma unroll
            for (int it = 0; it < 16; it++) {
                int cid = tid + it * 256;
                int c = cid >> 4, jc = (cid & 15) * 4;
                cpa16(smb + (FA4_SMV + nb * FA4_VBUF + c * FA4_VSTRIDE + jc) * 4,
                      Vb + (size_t)c * NN + j0n + jc);
            }
            cp_commit();
        }

        const float* Ks = sm + FA4_SMK + cur * FA4_KBUF;
        const float* Vs = sm + FA4_SMV + cur * FA4_VBUF;

        float s[8][4];
#pragma unroll
        for (int nt = 0; nt < 8; nt++)
#pragma unroll
            for (int e = 0; e < 4; e++) s[nt][e] = 0.f;

#pragma unroll
        for (int kk = 0; kk < 4; kk++) {
            const int d0 = 8 * kk;
#pragma unroll
            for (int nt = 0; nt < 8; nt++) {
                uint32_t b0 = __float_as_uint(Ks[(d0 + qb) * FA4_KSTRIDE + 8 * nt + g]);
                uint32_t b1 = __float_as_uint(Ks[(d0 + qb + 4) * FA4_KSTRIDE + 8 * nt + g]);
                mma8(s[nt], aq[kk][0], aq[kk][1], aq[kk][2], aq[kk][3], b0, b1);
            }
        }

        {
            float pmlo = -1e30f, pmhi = -1e30f;
#pragma unroll
            for (int nt = 0; nt < 8; nt++) {
                pmlo = fmaxf(pmlo, fmaxf(s[nt][0], s[nt][1]));
                pmhi = fmaxf(pmhi, fmaxf(s[nt][2], s[nt][3]));
            }
            pmlo = fmaxf(pmlo, __shfl_xor_sync(0xffffffffu, pmlo, 1));
            pmlo = fmaxf(pmlo, __shfl_xor_sync(0xffffffffu, pmlo, 2));
            pmhi = fmaxf(pmhi, __shfl_xor_sync(0xffffffffu, pmhi, 1));
            pmhi = fmaxf(pmhi, __shfl_xor_sync(0xffffffffu, pmhi, 2));

            float mlo_n = fmaxf(mlo, pmlo);
            float mhi_n = fmaxf(mhi, pmhi);
            float alo = __expf(mlo - mlo_n);
            float ahi = __expf(mhi - mhi_n);

            float slo = 0.f, shi = 0.f;
#pragma unroll
            for (int nt = 0; nt < 8; nt++) {
                s[nt][0] = __expf(s[nt][0] - mlo_n);
                s[nt][1] = __expf(s[nt][1] - mlo_n);
                s[nt][2] = __expf(s[nt][2] - mhi_n);
                s[nt][3] = __expf(s[nt][3] - mhi_n);
                slo += s[nt][0] + s[nt][1];
                shi += s[nt][2] + s[nt][3];
            }
            slo += __shfl_xor_sync(0xffffffffu, slo, 1);
            slo += __shfl_xor_sync(0xffffffffu, slo, 2);
            shi += __shfl_xor_sync(0xffffffffu, shi, 1);
            shi += __shfl_xor_sync(0xffffffffu, shi, 2);

            llo = llo * alo + slo;
            lhi = lhi * ahi + shi;
            mlo = mlo_n; mhi = mhi_n;

#pragma unroll
            for (int ct = 0; ct < 16; ct++) {
                acc[ct][0] *= alo; acc[ct][1] *= alo;
                acc[ct][2] *= ahi; acc[ct][3] *= ahi;
            }
        }

#pragma unroll
        for (int kk = 0; kk < 8; kk++) {
            float x0 = __shfl_sync(0xffffffffu, s[kk][0], srcA);
            float x1 = __shfl_sync(0xffffffffu, s[kk][1], srcA);
            float y0 = __shfl_sync(0xffffffffu, s[kk][0], srcB);
            float y1 = __shfl_sync(0xffffffffu, s[kk][1], srcB);
            float z0 = __shfl_sync(0xffffffffu, s[kk][2], srcA);
            float z1 = __shfl_sync(0xffffffffu, s[kk][3], srcA);
            float w0 = __shfl_sync(0xffffffffu, s[kk][2], srcB);
            float w1 = __shfl_sync(0xffffffffu, s[kk][3], srcB);
            uint32_t a0 = __float_as_uint(odd ? x1 : x0);
            uint32_t a1 = __float_as_uint(odd ? z1 : z0);
            uint32_t a2 = __float_as_uint(odd ? y1 : y0);
            uint32_t a3 = __float_as_uint(odd ? w1 : w0);

            const int jk = 8 * kk;
#pragma unroll
            for (int ct = 0; ct < 16; ct++) {
                const int c0 = 128 * cw + 8 * ct;
                uint32_t b0 = __float_as_uint(Vs[(c0 + g) * FA4_VSTRIDE + jk + qb]);
                uint32_t b1 = __float_as_uint(Vs[(c0 + g) * FA4_VSTRIDE + jk + qb + 4]);
                mma8(acc[ct], a0, a1, a2, a3, b0, b1);
            }
        }
    }
    __syncthreads();

    const float lilo = 1.f / llo;
    const float lihi = 1.f / lhi;
    float* smO = sm + FA4_SMV;

    for (int p = 0; p < 2; p++) {
        __syncthreads();
        if (cw == p) {
#pragma unroll
            for (int ct = 0; ct < 16; ct++) {
                const int rr = 16 * wm + g;
                const int cl = 8 * ct + 2 * qb;
                smO[cl * FA4_VSTRIDE + rr]           = acc[ct][0] * lilo;
                smO[(cl + 1) * FA4_VSTRIDE + rr]     = acc[ct][1] * lilo;
                smO[cl * FA4_VSTRIDE + rr + 8]       = acc[ct][2] * lihi;
                smO[(cl + 1) * FA4_VSTRIDE + rr + 8] = acc[ct][3] * lihi;
            }
        }
        __syncthreads();
        for (int idx = tid; idx < 128 * 16; idx += 256) {
            int c = idx >> 4, i4 = idx & 15;
            float4 v = *reinterpret_cast<float4*>(smO + c * FA4_VSTRIDE + i4 * 4);
            *reinterpret_cast<float4*>(
                O + ((size_t)(b * CC + 128 * p + c)) * NN + i0 + i4 * 4) = v;
        }
    }
}

// ---------------- combine: out = x + gamma*(attn + d1 + d3) ----------------------
// grid (1024, 1, BB); d1 has batch stride OP*NN, others CC*NN.
__global__ void combine_kernel(const float* __restrict__ x, const float* __restrict__ o,
                               const float* __restrict__ d1, const float* __restrict__ d3,
                               const float* __restrict__ gamma, float* __restrict__ out)
{
    const int b = blockIdx.z;
    const float4* xp = (const float4*)(x + (size_t)b * CC * NN);
    const float4* op = (const float4*)(o + (size_t)b * CC * NN);
    const float4* dp = (const float4*)(d1 + (size_t)b * OP * NN);
    const float4* ep = (const float4*)(d3 + (size_t)b * CC * NN);
    float4* outp = (float4*)(out + (size_t)b * CC * NN);
    const float g = gamma[0];
    int i = blockIdx.x * blockDim.x + threadIdx.x;
    if (i < CC * NN / 4) {
        float4 xv = xp[i], ov = op[i], dv = dp[i], ev = ep[i];
        float4 r;
        r.x = xv.x + g * (ov.x + dv.x + ev.x);
        r.y = xv.y + g * (ov.y + dv.y + ev.y);
        r.z = xv.z + g * (ov.z + dv.z + ev.z);
        r.w = xv.w + g * (ov.w + dv.w + ev.w);
        outp[i] = r;
    }
}

// ---------------- host launcher --------------------------------------------------
extern "C" void kernel_launch(void* const* d_in, const int* in_sizes, int n_in,
                              void* d_out, int out_size)
{
    (void)in_sizes; (void)n_in; (void)out_size;

    const float* x1  = (const float*)d_in[0];
    const float* x2  = (const float*)d_in[1];
    const float* wq1 = (const float*)d_in[2];
    const float* bq1 = (const float*)d_in[3];
    const float* wk1 = (const float*)d_in[4];
    const float* bk1 = (const float*)d_in[5];
    const float* wv1 = (const float*)d_in[6];
    const float* bv1 = (const float*)d_in[7];
    const float* wq2 = (const float*)d_in[8];
    const float* bq2 = (const float*)d_in[9];
    const float* wk2 = (const float*)d_in[10];
    const float* bk2 = (const float*)d_in[11];
    const float* wv2 = (const float*)d_in[12];
    const float* bv2 = (const float*)d_in[13];
    const float* wd1 = (const float*)d_in[14];
    const float* bd1 = (const float*)d_in[15];
    const float* wd3 = (const float*)d_in[16];
    const float* bd3 = (const float*)d_in[17];
    const float* gm1 = (const float*)d_in[18];
    const float* gm2 = (const float*)d_in[19];
    float* out = (float*)d_out;

    float *p_pk, *p_d3, *p_o1, *p_o2;
    cudaGetSymbolAddress((void**)&p_pk, g_pk);
    cudaGetSymbolAddress((void**)&p_d3, g_d3);
    cudaGetSymbolAddress((void**)&p_o1, g_o1);
    cudaGetSymbolAddress((void**)&p_o2, g_o2);

    const size_t side_str = (size_t)BB * OP * NN;
    float* pk0 = p_pk;
    float* pk1 = p_pk + side_str;
    float* d3a = p_d3;
    float* d3b = p_d3 + (size_t)BB * CC * NN;
    const size_t bstr = (size_t)OP * NN;

    cudaFuncSetAttribute(conv3x3_mma,
                         cudaFuncAttributeMaxDynamicSharedMemorySize, CV_SMEM_BYTES);
    cudaFuncSetAttribute(flashattn_mma,
                         cudaFuncAttributeMaxDynamicSharedMemorySize, FA4_SMEM_BYTES);

    // 0: pack weights
    pack_weights<<<dim3(OP, 2), 256>>>(wv1, bv1, wd1, bd1, wq1, bq1, wk1, bk1,
                                       wv2, bv2, wq2, bq2, wk2, bk2);
    // 1: fused projections (both sides)
    proj_mma<<<dim3(NN / 128, OP / 64, 8), 256>>>(x1, x2);
    // 2: conv3x3 (both sides)
    conv3x3_mma<<<dim3(CC / 64, HH / 4, 8), 256, CV_SMEM_BYTES>>>(x1, x2, wd3, bd3);
    // 3: attention 1 (queries x1; keys/values x2)
    flashattn_mma<<<dim3(NN / 64, BB), 256, FA4_SMEM_BYTES>>>(
        pk0 + (size_t)512 * NN, pk1 + (size_t)544 * NN, pk1, p_o1, bstr);
    // 4: combine out1
    combine_kernel<<<dim3(1024, 1, BB), 256>>>(x1, p_o1, pk0 + (size_t)256 * NN,
                                               d3a, gm1, out);
    // 5: attention 2 (queries x2; keys/values x1)  <-- profiled launch
    flashattn_mma<<<dim3(NN / 64, BB), 256, FA4_SMEM_BYTES>>>(
        pk1 + (size_t)512 * NN, pk0 + (size_t)544 * NN, pk0, p_o2, bstr);
    // 6: combine out2
    combine_kernel<<<dim3(1024, 1, BB), 256>>>(x2, p_o2, pk1 + (size_t)256 * NN,
                                               d3b, gm2, out + (size_t)BB * CC * NN);
}